// round 12
// baseline (speedup 1.0000x reference)
#include <cuda_runtime.h>
#include <cuda_bf16.h>
#include <mma.h>
#include <math.h>
#include <stdint.h>

using namespace nvcuda;

#define TOKS    8192
#define DMODEL  1024
#define FEXP    512
#define NEXP    16
#define NROUTED 14
#define KROUTE  4
#define KSEL    6

#define BM 128
#define BN 64
#define BK 32
#define LDA 40       // A smem row stride (32 + 8 pad) -> 80B (16B-aligned)
#define LDB 72       // B smem row stride (64 + 8 pad) -> 144B (16B-aligned)

// ---------------- device scratch ---------------------------------------------
__device__ __align__(16) int   g_cnt[NEXP];
__device__ int   g_ok_mma, g_ok1, g_ok2;
__device__ __align__(16) int   g_tok[NEXP * TOKS];
__device__ __align__(16) int   g_slot[TOKS * KSEL];
__device__ __align__(16) float g_aff[NEXP * TOKS];
__device__ __align__(16) __nv_bfloat16 g_h_hi[(size_t)NEXP * TOKS * FEXP];  // H hi
__device__ __align__(16) __nv_bfloat16 g_h_lo[(size_t)NEXP * TOKS * FEXP];  // H lo
__device__ __align__(16) float g_hf[(size_t)NEXP * TOKS * FEXP];            // fb H (fp32)
__device__ __align__(16) float g_out_tc[(size_t)TOKS * DMODEL];             // TC accum

// ---------------- helpers ----------------------------------------------------
__device__ __forceinline__ unsigned short bf16bits(float f) {
    __nv_bfloat16 b = __float2bfloat16(f);
    return *reinterpret_cast<unsigned short*>(&b);
}
__device__ __forceinline__ float bf16val(unsigned short u) {
    __nv_bfloat16 b = *reinterpret_cast<__nv_bfloat16*>(&u);
    return __bfloat162float(b);
}
__device__ __forceinline__ void split4(float4 v, __nv_bfloat16* hi, __nv_bfloat16* lo) {
    unsigned short h0 = bf16bits(v.x), h1 = bf16bits(v.y);
    unsigned short h2 = bf16bits(v.z), h3 = bf16bits(v.w);
    unsigned short l0 = bf16bits(v.x - bf16val(h0));
    unsigned short l1 = bf16bits(v.y - bf16val(h1));
    unsigned short l2 = bf16bits(v.z - bf16val(h2));
    unsigned short l3 = bf16bits(v.w - bf16val(h3));
    *reinterpret_cast<uint2*>(hi) = make_uint2(
        (uint32_t)h0 | ((uint32_t)h1 << 16), (uint32_t)h2 | ((uint32_t)h3 << 16));
    *reinterpret_cast<uint2*>(lo) = make_uint2(
        (uint32_t)l0 | ((uint32_t)l1 << 16), (uint32_t)l2 | ((uint32_t)l3 << 16));
}

// ---------------- utility kernels -------------------------------------------
__global__ void zero_out_kernel(float* out, int n) {
    int i = blockIdx.x * blockDim.x + threadIdx.x;
    if (i < n) out[i] = 0.f;
}
__global__ void zero_misc_kernel() {
    if (threadIdx.x < NEXP) g_cnt[threadIdx.x] = 0;
    if (threadIdx.x == 0) { g_ok_mma = 1; g_ok1 = 1; g_ok2 = 1; }
}
__global__ void zero_tc_kernel() {
    int i = blockIdx.x * blockDim.x + threadIdx.x;
    if (i < TOKS * DMODEL) g_out_tc[i] = 0.f;
}

// ---------------- routing ---------------------------------------------------
__global__ __launch_bounds__(256) void routing_kernel(
    const float* __restrict__ sel_in,
    const float* __restrict__ expert_sel,
    const float* __restrict__ bias,
    float* __restrict__ out, int write_sel)
{
    const int t    = blockIdx.x;
    const int tid  = threadIdx.x;
    const int warp = tid >> 5, lane = tid & 31;
    __shared__ float logit[NEXP];

    const float* x = sel_in + (size_t)t * DMODEL;
    #pragma unroll
    for (int w = 0; w < 2; w++) {
        int e = warp * 2 + w;
        const float* wr = expert_sel + (size_t)e * DMODEL;
        float s = 0.f;
        for (int i = lane; i < DMODEL; i += 32) s += x[i] * wr[i];
        #pragma unroll
        for (int o = 16; o > 0; o >>= 1) s += __shfl_xor_sync(0xffffffffu, s, o);
        if (lane == 0) logit[e] = s;
    }
    __syncthreads();

    if (tid == 0) {
        float a[NEXP];
        #pragma unroll
        for (int e = 0; e < NEXP; e++) a[e] = 1.f / (1.f + expf(-logit[e]));

        int sel[KSEL]; float af[KSEL];
        bool taken[NROUTED];
        #pragma unroll
        for (int i = 0; i < NROUTED; i++) taken[i] = false;
        #pragma unroll
        for (int k = 0; k < KROUTE; k++) {
            float best = -1e30f; int bi = 0;
            for (int i = 0; i < NROUTED; i++) {
                float v = a[i] + bias[i];
                if (!taken[i] && v > best) { best = v; bi = i; }
            }
            taken[bi] = true; sel[k] = bi; af[k] = a[bi];
        }
        sel[4] = NROUTED;     af[4] = a[NROUTED];
        sel[5] = NROUTED + 1; af[5] = a[NROUTED + 1];

        #pragma unroll
        for (int k = 0; k < KSEL; k++) {
            int e   = sel[k];
            int pos = atomicAdd(&g_cnt[e], 1);
            g_tok[e * TOKS + pos] = t;
            g_aff[e * TOKS + pos] = af[k];
            g_slot[t * KSEL + k] = pos;
            if (write_sel)
                out[(size_t)TOKS * DMODEL + (size_t)t * KSEL + k] = (float)e;
        }
    }
}

// ---------------- mma self-test (1 warp) -------------------------------------
__global__ void mma_selftest_kernel() {
    __shared__ __nv_bfloat16 a[16 * LDA];
    __shared__ __nv_bfloat16 b[16 * LDB];
    __shared__ float ep[256];
    const int lane = threadIdx.x;
    for (int i = lane; i < 16 * LDA; i += 32) a[i] = __float2bfloat16(0.f);
    for (int i = lane; i < 16 * LDB; i += 32) b[i] = __float2bfloat16(0.f);
    __syncwarp();
    for (int i = lane; i < 256; i += 32) {
        int m = i >> 4, k = i & 15;
        a[m * LDA + k] = __float2bfloat16(0.125f * (float)((m * 16 + k) % 13 - 6));
        b[m * LDB + k] = __float2bfloat16(0.25f  * (float)((m * 7  + k) % 11 - 5));
    }
    __syncwarp();
    wmma::fragment<wmma::matrix_a, 16, 16, 16, __nv_bfloat16, wmma::row_major> fa;
    wmma::fragment<wmma::matrix_b, 16, 16, 16, __nv_bfloat16, wmma::row_major> fb;
    wmma::fragment<wmma::accumulator, 16, 16, 16, float> fc;
    wmma::fill_fragment(fc, 0.f);
    wmma::load_matrix_sync(fa, a, LDA);
    wmma::load_matrix_sync(fb, b, LDB);
    wmma::mma_sync(fc, fa, fb, fc);
    wmma::store_matrix_sync(ep, fc, 16, wmma::mem_row_major);
    __syncwarp();
    for (int i = lane; i < 256; i += 32) {
        int m = i >> 4, n = i & 15;
        float ref = 0.f;
        for (int k = 0; k < 16; k++)
            ref += 0.125f * (float)((m * 16 + k) % 13 - 6)
                 * 0.25f  * (float)((k * 7  + n) % 11 - 5);
        if (fabsf(ep[i] - ref) > 1e-3f) g_ok_mma = 0;
    }
}

// ---------------- WMMA grouped GEMM (128x64xBK32) ---------------------------
struct __align__(16) GemmSmem {
    int   toks[BM];
    float affs[BM];
    union {
        struct {
            __nv_bfloat16 a_hi[BM * LDA];   // 10240 B
            __nv_bfloat16 a_lo[BM * LDA];
            __nv_bfloat16 b_hi[BK * LDB];   //  4608 B
            __nv_bfloat16 b_lo[BK * LDB];
        } t;
        float epi[8 * 1024];                // 32768 B (post-loop reuse)
    } u;
};

// 3-term wmma over one BK=32 chunk; warp tile 32(m) x 32(n); 8 warps = 4m x 2n
__device__ __forceinline__ void mma_stage(
    const GemmSmem& s, int wm, int wn,
    wmma::fragment<wmma::accumulator, 16, 16, 16, float> (&acc)[2][2])
{
    wmma::fragment<wmma::matrix_a, 16, 16, 16, __nv_bfloat16, wmma::row_major> fa_hi, fa_lo;
    wmma::fragment<wmma::matrix_b, 16, 16, 16, __nv_bfloat16, wmma::row_major> fb_hi[2], fb_lo[2];
    #pragma unroll
    for (int ks = 0; ks < BK; ks += 16) {
        #pragma unroll
        for (int nt = 0; nt < 2; nt++) {
            wmma::load_matrix_sync(fb_hi[nt], &s.u.t.b_hi[ks * LDB + wn + nt * 16], LDB);
            wmma::load_matrix_sync(fb_lo[nt], &s.u.t.b_lo[ks * LDB + wn + nt * 16], LDB);
        }
        #pragma unroll
        for (int mt = 0; mt < 2; mt++) {
            wmma::load_matrix_sync(fa_hi, &s.u.t.a_hi[(wm + mt * 16) * LDA + ks], LDA);
            wmma::load_matrix_sync(fa_lo, &s.u.t.a_lo[(wm + mt * 16) * LDA + ks], LDA);
            #pragma unroll
            for (int nt = 0; nt < 2; nt++) {
                wmma::mma_sync(acc[mt][nt], fa_hi, fb_hi[nt], acc[mt][nt]);
                wmma::mma_sync(acc[mt][nt], fa_hi, fb_lo[nt], acc[mt][nt]);
                wmma::mma_sync(acc[mt][nt], fa_lo, fb_hi[nt], acc[mt][nt]);
            }
        }
    }
}

// GEMM1: H[slot][f] = silu( x[tok] @ keys[e] )[f] * aff  -> bf16 hi/lo
__global__ __launch_bounds__(256, 1) void moe_gemm1(
    const float* __restrict__ x, const float* __restrict__ keys)
{
    const int e   = blockIdx.y;
    const int cnt = g_cnt[e];
    const int m0  = blockIdx.x * BM;
    if (m0 >= cnt) return;
    const int n0  = blockIdx.z * BN;

    __shared__ GemmSmem s;
    const int tid = threadIdx.x, w = tid >> 5, lane = tid & 31;
    const int wm = (w >> 1) * 32, wn = (w & 1) * 32;
    const int ar = tid >> 1, aq = tid & 1;     // A: row, 16-col half
    const int bk = tid >> 3, bg = tid & 7;     // B: k-row, 8-col group

    if (tid < BM) {
        int mg = m0 + tid; bool v = mg < cnt;
        s.toks[tid] = v ? g_tok[e * TOKS + mg] : 0;
        s.affs[tid] = v ? g_aff[e * TOKS + mg] : 0.f;
    }
    __syncthreads();

    wmma::fragment<wmma::accumulator, 16, 16, 16, float> acc[2][2];
    #pragma unroll
    for (int i = 0; i < 2; i++)
        #pragma unroll
        for (int j = 0; j < 2; j++) wmma::fill_fragment(acc[i][j], 0.f);

    const size_t arowb = (size_t)s.toks[ar] * DMODEL + aq * 16;
    float4 pa[4], pb[2];
    #pragma unroll
    for (int q = 0; q < 4; q++) pa[q] = *(const float4*)(x + arowb + q * 4);
    {
        const float* bp = keys + ((size_t)e * DMODEL + bk) * FEXP + n0 + bg * 8;
        pb[0] = *(const float4*)(bp);
        pb[1] = *(const float4*)(bp + 4);
    }

    const int NC = DMODEL / BK;    // 32
    for (int c = 0; c < NC; c++) {
        __syncthreads();
        #pragma unroll
        for (int q = 0; q < 4; q++)
            split4(pa[q], &s.u.t.a_hi[ar * LDA + aq * 16 + q * 4],
                          &s.u.t.a_lo[ar * LDA + aq * 16 + q * 4]);
        split4(pb[0], &s.u.t.b_hi[bk * LDB + bg * 8],     &s.u.t.b_lo[bk * LDB + bg * 8]);
        split4(pb[1], &s.u.t.b_hi[bk * LDB + bg * 8 + 4], &s.u.t.b_lo[bk * LDB + bg * 8 + 4]);
        __syncthreads();
        if (c + 1 < NC) {
            int k0 = (c + 1) * BK;
            #pragma unroll
            for (int q = 0; q < 4; q++)
                pa[q] = *(const float4*)(x + arowb + k0 + q * 4);
            const float* bp = keys + ((size_t)e * DMODEL + k0 + bk) * FEXP + n0 + bg * 8;
            pb[0] = *(const float4*)(bp);
            pb[1] = *(const float4*)(bp + 4);
        }
        mma_stage(s, wm, wn, acc);
    }
    __syncthreads();   // all mma reads done before epi overlays tiles

    float* ep = s.u.epi + w * 1024;
    #pragma unroll
    for (int mt = 0; mt < 2; mt++)
        #pragma unroll
        for (int nt = 0; nt < 2; nt++)
            wmma::store_matrix_sync(ep + (mt * 2 + nt) * 256, acc[mt][nt], 16,
                                    wmma::mem_row_major);
    __syncwarp();

    const int mloc = wm + lane;          // lane -> row within warp tile
    const int mt = lane >> 4, lr = lane & 15;
    if (m0 + mloc < cnt) {
        float aff = s.affs[mloc];
        size_t rowb = ((size_t)e * TOKS + m0 + mloc) * FEXP + n0 + wn;
        unsigned short* dh = reinterpret_cast<unsigned short*>(g_h_hi) + rowb;
        unsigned short* dl = reinterpret_cast<unsigned short*>(g_h_lo) + rowb;
        #pragma unroll
        for (int nt = 0; nt < 2; nt++) {
            #pragma unroll
            for (int p = 0; p < 16; p += 2) {
                float v0 = ep[(mt * 2 + nt) * 256 + lr * 16 + p];
                float v1 = ep[(mt * 2 + nt) * 256 + lr * 16 + p + 1];
                float h0 = v0 / (1.f + __expf(-v0)) * aff;
                float h1 = v1 / (1.f + __expf(-v1)) * aff;
                unsigned short hb0 = bf16bits(h0), hb1 = bf16bits(h1);
                unsigned short lb0 = bf16bits(h0 - bf16val(hb0));
                unsigned short lb1 = bf16bits(h1 - bf16val(hb1));
                *reinterpret_cast<uint32_t*>(dh + nt * 16 + p)
                    = (uint32_t)hb0 | ((uint32_t)hb1 << 16);
                *reinterpret_cast<uint32_t*>(dl + nt * 16 + p)
                    = (uint32_t)lb0 | ((uint32_t)lb1 << 16);
            }
        }
    }
}

// GEMM2: g_out_tc[tok][d] += H[slot] @ values[e] ; A = bf16 H (direct copy)
__global__ __launch_bounds__(256, 1) void moe_gemm2(const float* __restrict__ values) {
    const int e   = blockIdx.y;
    const int cnt = g_cnt[e];
    const int m0  = blockIdx.x * BM;
    if (m0 >= cnt) return;
    const int n0  = blockIdx.z * BN;

    __shared__ GemmSmem s;
    const int tid = threadIdx.x, w = tid >> 5, lane = tid & 31;
    const int wm = (w >> 1) * 32, wn = (w & 1) * 32;
    const int ar = tid >> 1, aq = tid & 1;
    const int bk = tid >> 3, bg = tid & 7;

    if (tid < BM) {
        int mg = m0 + tid;
        s.toks[tid] = (mg < cnt) ? g_tok[e * TOKS + mg] : 0;
    }
    __syncthreads();

    wmma::fragment<wmma::accumulator, 16, 16, 16, float> acc[2][2];
    #pragma unroll
    for (int i = 0; i < 2; i++)
        #pragma unroll
        for (int j = 0; j < 2; j++) wmma::fill_fragment(acc[i][j], 0.f);

    const size_t ab = ((size_t)e * TOKS + m0 + ar) * FEXP + aq * 16;
    uint4 ph[2], pl[2];
    ph[0] = *(const uint4*)(reinterpret_cast<const unsigned short*>(g_h_hi) + ab);
    ph[1] = *(const uint4*)(reinterpret_cast<const unsigned short*>(g_h_hi) + ab + 8);
    pl[0] = *(const uint4*)(reinterpret_cast<const unsigned short*>(g_h_lo) + ab);
    pl[1] = *(const uint4*)(reinterpret_cast<const unsigned short*>(g_h_lo) + ab + 8);
    float4 pb[2];
    {
        const float* bp = values + ((size_t)e * FEXP + bk) * DMODEL + n0 + bg * 8;
        pb[0] = *(const float4*)(bp);
        pb[1] = *(const float4*)(bp + 4);
    }

    const int NC = FEXP / BK;    // 16
    for (int c = 0; c < NC; c++) {
        __syncthreads();
        *reinterpret_cast<uint4*>(&s.u.t.a_hi[ar * LDA + aq * 16])     = ph[0];
        *reinterpret_cast<uint4*>(&s.u.t.a_hi[ar * LDA + aq * 16 + 8]) = ph[1];
        *reinterpret_cast<uint4*>(&s.u.t.a_lo[ar * LDA + aq * 16])     = pl[0];
        *reinterpret_cast<uint4*>(&s.u.t.a_lo[ar * LDA + aq * 16 + 8]) = pl[1];
        split4(pb[0], &s.u.t.b_hi[bk * LDB + bg * 8],     &s.u.t.b_lo[bk * LDB + bg * 8]);
        split4(pb[1], &s.u.t.b_hi[bk * LDB + bg * 8 + 4], &s.u.t.b_lo[bk * LDB + bg * 8 + 4]);
        __syncthreads();
        if (c + 1 < NC) {
            int k0 = (c + 1) * BK;
            ph[0] = *(const uint4*)(reinterpret_cast<const unsigned short*>(g_h_hi) + ab + k0);
            ph[1] = *(const uint4*)(reinterpret_cast<const unsigned short*>(g_h_hi) + ab + k0 + 8);
            pl[0] = *(const uint4*)(reinterpret_cast<const unsigned short*>(g_h_lo) + ab + k0);
            pl[1] = *(const uint4*)(reinterpret_cast<const unsigned short*>(g_h_lo) + ab + k0 + 8);
            const float* bp = values + ((size_t)e * FEXP + k0 + bk) * DMODEL + n0 + bg * 8;
            pb[0] = *(const float4*)(bp);
            pb[1] = *(const float4*)(bp + 4);
        }
        mma_stage(s, wm, wn, acc);
    }
    __syncthreads();

    float* ep = s.u.epi + w * 1024;
    #pragma unroll
    for (int mt = 0; mt < 2; mt++)
        #pragma unroll
        for (int nt = 0; nt < 2; nt++)
            wmma::store_matrix_sync(ep + (mt * 2 + nt) * 256, acc[mt][nt], 16,
                                    wmma::mem_row_major);
    __syncwarp();

    const int mloc = wm + lane;
    const int mt = lane >> 4, lr = lane & 15;
    if (m0 + mloc < cnt) {
        float* dst = g_out_tc + (size_t)s.toks[mloc] * DMODEL + n0 + wn;
        #pragma unroll
        for (int nt = 0; nt < 2; nt++)
            #pragma unroll
            for (int p = 0; p < 16; p++)
                atomicAdd(dst + nt * 16 + p, ep[(mt * 2 + nt) * 256 + lr * 16 + p]);
    }
}

// ---------------- verify TC on 4 probe tokens --------------------------------
__global__ __launch_bounds__(256) void verify_kernel(
    const float* __restrict__ x, const float* __restrict__ sel_in,
    const float* __restrict__ keys, const float* __restrict__ values,
    const float* __restrict__ expert_sel, const float* __restrict__ bias)
{
    const int t   = (blockIdx.x * 2731 + 17) & (TOKS - 1);
    const int tid = threadIdx.x;
    const int warp = tid >> 5, lane = tid & 31;
    __shared__ float logit[NEXP];
    __shared__ int   sel[KSEL];
    __shared__ float aff[KSEL];
    __shared__ float hbuf[FEXP];

    const float* xs = sel_in + (size_t)t * DMODEL;
    #pragma unroll
    for (int w = 0; w < 2; w++) {
        int e = warp * 2 + w;
        const float* wr = expert_sel + (size_t)e * DMODEL;
        float s = 0.f;
        for (int i = lane; i < DMODEL; i += 32) s += xs[i] * wr[i];
        #pragma unroll
        for (int o = 16; o > 0; o >>= 1) s += __shfl_xor_sync(0xffffffffu, s, o);
        if (lane == 0) logit[e] = s;
    }
    __syncthreads();

    if (tid == 0) {
        float a[NEXP];
        #pragma unroll
        for (int e = 0; e < NEXP; e++) a[e] = 1.f / (1.f + expf(-logit[e]));
        bool taken[NROUTED];
        #pragma unroll
        for (int i = 0; i < NROUTED; i++) taken[i] = false;
        #pragma unroll
        for (int k = 0; k < KROUTE; k++) {
            float best = -1e30f; int bi = 0;
            for (int i = 0; i < NROUTED; i++) {
                float v = a[i] + bias[i];
                if (!taken[i] && v > best) { best = v; bi = i; }
            }
            taken[bi] = true; sel[k] = bi; aff[k] = a[bi];
        }
        sel[4] = NROUTED;     aff[4] = a[NROUTED];
        sel[5] = NROUTED + 1; aff[5] = a[NROUTED + 1];
    }
    __syncthreads();

    const float* xt = x + (size_t)t * DMODEL;
    const int d = tid;
    float acc = 0.f;
    for (int k = 0; k < KSEL; k++) {
        int e = sel[k];
        int pos = g_slot[t * KSEL + k];
        for (int f = tid; f < FEXP; f += 256) {
            float s = 0.f;
            const float* kw = keys + ((size_t)e * DMODEL) * FEXP + f;
            for (int kk = 0; kk < DMODEL; kk++) s += xt[kk] * kw[(size_t)kk * FEXP];
            float hv = s / (1.f + expf(-s)) * aff[k];
            hbuf[f] = hv;
            size_t hidx = ((size_t)e * TOKS + pos) * FEXP + f;
            float hs = bf16val(reinterpret_cast<unsigned short*>(g_h_hi)[hidx])
                     + bf16val(reinterpret_cast<unsigned short*>(g_h_lo)[hidx]);
            if (fabsf(hs - hv) > 5e-4f * fmaxf(fabsf(hv), 0.25f)) g_ok1 = 0;
        }
        __syncthreads();
        float a2 = 0.f;
        const float* vw = values + ((size_t)e * FEXP) * DMODEL + d;
        for (int f = 0; f < FEXP; f++) a2 += hbuf[f] * vw[(size_t)f * DMODEL];
        acc += a2;
        __syncthreads();
    }

    float got = g_out_tc[(size_t)t * DMODEL + d];
    if (fabsf(got - acc) > 5e-4f * fmaxf(fabsf(acc), 0.5f)) g_ok2 = 0;
}

// ---------------- fp32 SIMT fallback (round-1 proven) ------------------------
__global__ __launch_bounds__(256) void fb_gemm1(
    const float* __restrict__ xs, const float* __restrict__ keys)
{
    if (g_ok1) return;
    const int e   = blockIdx.y;
    const int cnt = g_cnt[e];
    const int m0  = blockIdx.x * 64;
    if (m0 >= cnt) return;
    const int n0  = blockIdx.z * 64;

    __shared__ float As[16][64];
    __shared__ float Bs[16][64];
    __shared__ int   toks[64];
    __shared__ float affs[64];

    const int tid = threadIdx.x;
    if (tid < 64) {
        int mg = m0 + tid;
        toks[tid] = (mg < cnt) ? g_tok[e * TOKS + mg] : 0;
        affs[tid] = (mg < cnt) ? g_aff[e * TOKS + mg] : 0.f;
    }
    __syncthreads();

    const int ty  = tid >> 4, tx  = tid & 15;
    const int am  = tid >> 2, akq = tid & 3;
    const int bk  = tid >> 4, bnq = tid & 15;
    const bool avalid = (m0 + am) < cnt;
    const float* arow = xs + (size_t)toks[am] * DMODEL;

    float acc[4][4];
    #pragma unroll
    for (int i = 0; i < 4; i++)
        #pragma unroll
        for (int jj = 0; jj < 4; jj++) acc[i][jj] = 0.f;

    for (int k0 = 0; k0 < DMODEL; k0 += 16) {
        float4 av = avalid ? *(const float4*)(arow + k0 + akq * 4)
                           : make_float4(0.f, 0.f, 0.f, 0.f);
        float4 bv = *(const float4*)(keys +
                    ((size_t)e * DMODEL + k0 + bk) * FEXP + n0 + bnq * 4);
        As[akq * 4 + 0][am] = av.x;
        As[akq * 4 + 1][am] = av.y;
        As[akq * 4 + 2][am] = av.z;
        As[akq * 4 + 3][am] = av.w;
        *(float4*)&Bs[bk][bnq * 4] = bv;
        __syncthreads();
        #pragma unroll
        for (int kk = 0; kk < 16; kk++) {
            float4 a = *(const float4*)&As[kk][ty * 4];
            float4 b = *(const float4*)&Bs[kk][tx * 4];
            float ar[4] = {a.x, a.y, a.z, a.w};
            float br[4] = {b.x, b.y, b.z, b.w};
            #pragma unroll
            for (int i = 0; i < 4; i++)
                #pragma unroll
                for (int jj = 0; jj < 4; jj++) acc[i][jj] += ar[i] * br[jj];
        }
        __syncthreads();
    }

    const size_t hbase = ((size_t)e * TOKS + m0) * FEXP + n0;
    #pragma unroll
    for (int i = 0; i < 4; i++) {
        int m = ty * 4 + i;
        if (m0 + m < cnt) {
            float afv = affs[m];
            #pragma unroll
            for (int jj = 0; jj < 4; jj++) {
                float v = acc[i][jj];
                g_hf[hbase + (size_t)m * FEXP + tx * 4 + jj] =
                    v / (1.f + __expf(-v)) * afv;
            }
        }
    }
}

// rebuild fp32 H from verified bf16 H when only stage-2 failed
__global__ __launch_bounds__(256) void h_conv_kernel() {
    if (!(g_ok1 && !g_ok2)) return;
    size_t i = (size_t)blockIdx.x * blockDim.x + threadIdx.x;
    if (i >= (size_t)NEXP * TOKS * FEXP / 4) return;
    ushort4 h = reinterpret_cast<const ushort4*>(g_h_hi)[i];
    ushort4 l = reinterpret_cast<const ushort4*>(g_h_lo)[i];
    float4 v;
    v.x = bf16val(h.x) + bf16val(l.x);
    v.y = bf16val(h.y) + bf16val(l.y);
    v.z = bf16val(h.z) + bf16val(l.z);
    v.w = bf16val(h.w) + bf16val(l.w);
    reinterpret_cast<float4*>(g_hf)[i] = v;
}

__global__ __launch_bounds__(256) void fb_gemm2(
    const float* __restrict__ values, float* __restrict__ out)
{
    if (g_ok1 && g_ok2) return;
    const int e   = blockIdx.y;
    const int cnt = g_cnt[e];
    const int m0  = blockIdx.x * 64;
    if (m0 >= cnt) return;
    const int n0  = blockIdx.z * 64;

    __shared__ float As[16][64];
    __shared__ float Bs[16][64];
    __shared__ int   toks[64];

    const int tid = threadIdx.x;
    if (tid < 64) {
        int mg = m0 + tid;
        toks[tid] = (mg < cnt) ? g_tok[e * TOKS + mg] : 0;
    }
    __syncthreads();

    const int ty  = tid >> 4, tx  = tid & 15;
    const int am  = tid >> 2, akq = tid & 3;
    const int bk  = tid >> 4, bnq = tid & 15;
    const bool avalid = (m0 + am) < cnt;
    const float* arow = g_hf + ((size_t)e * TOKS + m0 + am) * FEXP;

    float acc[4][4];
    #pragma unroll
    for (int i = 0; i < 4; i++)
        #pragma unroll
        for (int jj = 0; jj < 4; jj++) acc[i][jj] = 0.f;

    for (int k0 = 0; k0 < FEXP; k0 += 16) {
        float4 av = avalid ? *(const float4*)(arow + k0 + akq * 4)
                           : make_float4(0.f, 0.f, 0.f, 0.f);
        float4 bv = *(const float4*)(values +
                    ((size_t)e * FEXP + k0 + bk) * DMODEL + n0 + bnq * 4);
        As[akq * 4 + 0][am] = av.x;
        As[akq * 4 + 1][am] = av.y;
        As[akq * 4 + 2][am] = av.z;
        As[akq * 4 + 3][am] = av.w;
        *(float4*)&Bs[bk][bnq * 4] = bv;
        __syncthreads();
        #pragma unroll
        for (int kk = 0; kk < 16; kk++) {
            float4 a = *(const float4*)&As[kk][ty * 4];
            float4 b = *(const float4*)&Bs[kk][tx * 4];
            float ar[4] = {a.x, a.y, a.z, a.w};
            float br[4] = {b.x, b.y, b.z, b.w};
            #pragma unroll
            for (int i = 0; i < 4; i++)
                #pragma unroll
                for (int jj = 0; jj < 4; jj++) acc[i][jj] += ar[i] * br[jj];
        }
        __syncthreads();
    }

    #pragma unroll
    for (int i = 0; i < 4; i++) {
        int m = ty * 4 + i;
        if (m0 + m < cnt) {
            int t = toks[m];
            #pragma unroll
            for (int jj = 0; jj < 4; jj++)
                atomicAdd(&out[(size_t)t * DMODEL + n0 + tx * 4 + jj], acc[i][jj]);
        }
    }
}

// ---------------- commit + diagnostic delay ----------------------------------
__global__ void commit_kernel(float* __restrict__ out) {
    if (!(g_ok1 && g_ok2)) return;
    int i = blockIdx.x * blockDim.x + threadIdx.x;
    if (i < TOKS * DMODEL) out[i] = g_out_tc[i];
}

__global__ void diag_delay_kernel() {
    long long target = 0;
    if (!g_ok_mma) target += 5000000LL;             // ~3 ms
    if (!g_ok1)    target += 2500000LL;             // ~1.5 ms
    else if (!g_ok2) target += 1250000LL;           // ~0.75 ms
    if (target == 0) return;
    long long s = clock64();
    while (clock64() - s < target) { }
}

// ---------------- launch -----------------------------------------------------
extern "C" void kernel_launch(void* const* d_in, const int* in_sizes, int n_in,
                              void* d_out, int out_size) {
    const float* token_stream = (const float*)d_in[0];
    const float* sel_input    = (const float*)d_in[1];
    const float* keys         = (const float*)d_in[2];
    const float* values       = (const float*)d_in[3];
    const float* esel         = (const float*)d_in[4];
    const float* bias         = (const float*)d_in[5];
    float* out = (float*)d_out;

    const int write_sel = (out_size >= TOKS * DMODEL + TOKS * KSEL) ? 1 : 0;

    zero_out_kernel<<<(TOKS * DMODEL + 511) / 512, 512>>>(out, TOKS * DMODEL);
    zero_misc_kernel<<<1, 32>>>();
    zero_tc_kernel<<<(TOKS * DMODEL + 511) / 512, 512>>>();

    routing_kernel<<<TOKS, 256>>>(sel_input, esel, bias, out, write_sel);
    mma_selftest_kernel<<<1, 32>>>();

    // TC path
    dim3 g1(TOKS / BM, NEXP, FEXP / BN);       // (64, 16, 8)
    moe_gemm1<<<g1, 256>>>(token_stream, keys);
    dim3 g2(TOKS / BM, NEXP, DMODEL / BN);     // (64, 16, 16)
    moe_gemm2<<<g2, 256>>>(values);

    verify_kernel<<<4, 256>>>(token_stream, sel_input, keys, values, esel, bias);

    // tiered fallback
    dim3 f1(TOKS / 64, NEXP, FEXP / 64);
    fb_gemm1<<<f1, 256>>>(token_stream, keys);
    h_conv_kernel<<<(int)(((size_t)NEXP * TOKS * FEXP / 4 + 255) / 256), 256>>>();
    dim3 f2(TOKS / 64, NEXP, DMODEL / 64);
    fb_gemm2<<<f2, 256>>>(values, out);

    commit_kernel<<<(TOKS * DMODEL + 511) / 512, 512>>>(out);
    diag_delay_kernel<<<1, 1>>>();
}

// round 13
// speedup vs baseline: 1.1034x; 1.1034x over previous
#include <cuda_runtime.h>
#include <cuda_bf16.h>
#include <mma.h>
#include <math.h>
#include <stdint.h>

using namespace nvcuda;

#define TOKS    8192
#define DMODEL  1024
#define FEXP    512
#define NEXP    16
#define NROUTED 14
#define KROUTE  4
#define KSEL    6

#define BM 64
#define BN 64
#define BK 32
#define LDA 40       // A smem row stride (32 + 8 pad) -> 80B
#define LDB 72       // B smem row stride (64 + 8 pad) -> 144B

// ---------------- device scratch ---------------------------------------------
__device__ __align__(16) int   g_cnt[NEXP];
__device__ int   g_ok_mma, g_ok1, g_ok2;
__device__ __align__(16) int   g_tok[NEXP * TOKS];
__device__ __align__(16) int   g_slot[TOKS * KSEL];
__device__ __align__(16) float g_aff[NEXP * TOKS];
__device__ __align__(16) __nv_bfloat16 g_h_hi[(size_t)NEXP * TOKS * FEXP];
__device__ __align__(16) __nv_bfloat16 g_h_lo[(size_t)NEXP * TOKS * FEXP];
__device__ __align__(16) float g_hf[(size_t)NEXP * TOKS * FEXP];     // fb H (fp32)
__device__ __align__(16) float g_out_tc[(size_t)TOKS * DMODEL];      // TC accum

// ---------------- helpers ----------------------------------------------------
__device__ __forceinline__ unsigned short bf16bits(float f) {
    __nv_bfloat16 b = __float2bfloat16(f);
    return *reinterpret_cast<unsigned short*>(&b);
}
__device__ __forceinline__ float bf16val(unsigned short u) {
    __nv_bfloat16 b = *reinterpret_cast<__nv_bfloat16*>(&u);
    return __bfloat162float(b);
}
__device__ __forceinline__ void split4(float4 v, __nv_bfloat16* hi, __nv_bfloat16* lo) {
    unsigned short h0 = bf16bits(v.x), h1 = bf16bits(v.y);
    unsigned short h2 = bf16bits(v.z), h3 = bf16bits(v.w);
    unsigned short l0 = bf16bits(v.x - bf16val(h0));
    unsigned short l1 = bf16bits(v.y - bf16val(h1));
    unsigned short l2 = bf16bits(v.z - bf16val(h2));
    unsigned short l3 = bf16bits(v.w - bf16val(h3));
    *reinterpret_cast<uint2*>(hi) = make_uint2(
        (uint32_t)h0 | ((uint32_t)h1 << 16), (uint32_t)h2 | ((uint32_t)h3 << 16));
    *reinterpret_cast<uint2*>(lo) = make_uint2(
        (uint32_t)l0 | ((uint32_t)l1 << 16), (uint32_t)l2 | ((uint32_t)l3 << 16));
}

// ---------------- utility kernels -------------------------------------------
__global__ void zero_out_kernel(float* out, int n) {
    int i = blockIdx.x * blockDim.x + threadIdx.x;
    if (i < n) out[i] = 0.f;
}
__global__ void zero_misc_kernel() {
    if (threadIdx.x < NEXP) g_cnt[threadIdx.x] = 0;
    if (threadIdx.x == 0) { g_ok_mma = 1; g_ok1 = 1; g_ok2 = 1; }
}
__global__ void zero_tc_kernel() {
    int i = blockIdx.x * blockDim.x + threadIdx.x;
    if (i < TOKS * DMODEL) g_out_tc[i] = 0.f;
}

// ---------------- routing ---------------------------------------------------
__global__ __launch_bounds__(256) void routing_kernel(
    const float* __restrict__ sel_in,
    const float* __restrict__ expert_sel,
    const float* __restrict__ bias,
    float* __restrict__ out, int write_sel)
{
    const int t    = blockIdx.x;
    const int tid  = threadIdx.x;
    const int warp = tid >> 5, lane = tid & 31;
    __shared__ float logit[NEXP];

    const float* x = sel_in + (size_t)t * DMODEL;
    #pragma unroll
    for (int w = 0; w < 2; w++) {
        int e = warp * 2 + w;
        const float* wr = expert_sel + (size_t)e * DMODEL;
        float s = 0.f;
        for (int i = lane; i < DMODEL; i += 32) s += x[i] * wr[i];
        #pragma unroll
        for (int o = 16; o > 0; o >>= 1) s += __shfl_xor_sync(0xffffffffu, s, o);
        if (lane == 0) logit[e] = s;
    }
    __syncthreads();

    if (tid == 0) {
        float a[NEXP];
        #pragma unroll
        for (int e = 0; e < NEXP; e++) a[e] = 1.f / (1.f + expf(-logit[e]));

        int sel[KSEL]; float af[KSEL];
        bool taken[NROUTED];
        #pragma unroll
        for (int i = 0; i < NROUTED; i++) taken[i] = false;
        #pragma unroll
        for (int k = 0; k < KROUTE; k++) {
            float best = -1e30f; int bi = 0;
            for (int i = 0; i < NROUTED; i++) {
                float v = a[i] + bias[i];
                if (!taken[i] && v > best) { best = v; bi = i; }
            }
            taken[bi] = true; sel[k] = bi; af[k] = a[bi];
        }
        sel[4] = NROUTED;     af[4] = a[NROUTED];
        sel[5] = NROUTED + 1; af[5] = a[NROUTED + 1];

        #pragma unroll
        for (int k = 0; k < KSEL; k++) {
            int e   = sel[k];
            int pos = atomicAdd(&g_cnt[e], 1);
            g_tok[e * TOKS + pos] = t;
            g_aff[e * TOKS + pos] = af[k];
            g_slot[t * KSEL + k] = pos;
            if (write_sel)
                out[(size_t)TOKS * DMODEL + (size_t)t * KSEL + k] = (float)e;
        }
    }
}

// ---------------- mma self-test (1 warp) -------------------------------------
__global__ void mma_selftest_kernel() {
    __shared__ __nv_bfloat16 a[16 * LDA];
    __shared__ __nv_bfloat16 b[16 * LDB];
    __shared__ float ep[256];
    const int lane = threadIdx.x;
    for (int i = lane; i < 16 * LDA; i += 32) a[i] = __float2bfloat16(0.f);
    for (int i = lane; i < 16 * LDB; i += 32) b[i] = __float2bfloat16(0.f);
    __syncwarp();
    for (int i = lane; i < 256; i += 32) {
        int m = i >> 4, k = i & 15;
        a[m * LDA + k] = __float2bfloat16(0.125f * (float)((m * 16 + k) % 13 - 6));
        b[m * LDB + k] = __float2bfloat16(0.25f  * (float)((m * 7  + k) % 11 - 5));
    }
    __syncwarp();
    wmma::fragment<wmma::matrix_a, 16, 16, 16, __nv_bfloat16, wmma::row_major> fa;
    wmma::fragment<wmma::matrix_b, 16, 16, 16, __nv_bfloat16, wmma::row_major> fb;
    wmma::fragment<wmma::accumulator, 16, 16, 16, float> fc;
    wmma::fill_fragment(fc, 0.f);
    wmma::load_matrix_sync(fa, a, LDA);
    wmma::load_matrix_sync(fb, b, LDB);
    wmma::mma_sync(fc, fa, fb, fc);
    wmma::store_matrix_sync(ep, fc, 16, wmma::mem_row_major);
    __syncwarp();
    for (int i = lane; i < 256; i += 32) {
        int m = i >> 4, n = i & 15;
        float ref = 0.f;
        for (int k = 0; k < 16; k++)
            ref += 0.125f * (float)((m * 16 + k) % 13 - 6)
                 * 0.25f  * (float)((k * 7  + n) % 11 - 5);
        if (fabsf(ep[i] - ref) > 1e-3f) g_ok_mma = 0;
    }
}

// ---------------- WMMA grouped GEMM (64x64xBK32, 2 CTAs/SM) -----------------
struct __align__(16) GemmSmem {
    int   toks[BM];
    float affs[BM];
    union {
        struct {
            __nv_bfloat16 a_hi[BM * LDA];   // 5120 B
            __nv_bfloat16 a_lo[BM * LDA];
            __nv_bfloat16 b_hi[BK * LDB];   // 4608 B
            __nv_bfloat16 b_lo[BK * LDB];
        } t;
        float epi[8 * 512];                 // 16384 B (post-loop reuse)
    } u;
};

// 3-term wmma over one BK=32 chunk; warp tile 32(m) x 16(n)
__device__ __forceinline__ void mma_stage(
    const GemmSmem& s, int wm, int wn,
    wmma::fragment<wmma::accumulator, 16, 16, 16, float> (&acc)[2])
{
    wmma::fragment<wmma::matrix_a, 16, 16, 16, __nv_bfloat16, wmma::row_major> fa_hi, fa_lo;
    wmma::fragment<wmma::matrix_b, 16, 16, 16, __nv_bfloat16, wmma::row_major> fb_hi, fb_lo;
    #pragma unroll
    for (int ks = 0; ks < BK; ks += 16) {
        wmma::load_matrix_sync(fb_hi, &s.u.t.b_hi[ks * LDB + wn], LDB);
        wmma::load_matrix_sync(fb_lo, &s.u.t.b_lo[ks * LDB + wn], LDB);
        #pragma unroll
        for (int mt = 0; mt < 2; mt++) {
            wmma::load_matrix_sync(fa_hi, &s.u.t.a_hi[(wm + mt * 16) * LDA + ks], LDA);
            wmma::load_matrix_sync(fa_lo, &s.u.t.a_lo[(wm + mt * 16) * LDA + ks], LDA);
            wmma::mma_sync(acc[mt], fa_hi, fb_hi, acc[mt]);
            wmma::mma_sync(acc[mt], fa_hi, fb_lo, acc[mt]);
            wmma::mma_sync(acc[mt], fa_lo, fb_hi, acc[mt]);
        }
    }
}

// GEMM1: H[slot][f] = silu( x[tok] @ keys[e] )[f] * aff  -> bf16 hi/lo
__global__ __launch_bounds__(256, 2) void moe_gemm1(
    const float* __restrict__ x, const float* __restrict__ keys)
{
    const int e   = blockIdx.y;
    const int cnt = g_cnt[e];
    const int m0  = blockIdx.x * BM;
    if (m0 >= cnt) return;
    const int n0  = blockIdx.z * BN;

    __shared__ GemmSmem s;
    const int tid = threadIdx.x, w = tid >> 5, lane = tid & 31;
    const int wm = (w & 1) * 32, wn = (w >> 1) * 16;
    const int ar = tid >> 2, aq = tid & 3;     // A: row, col-quad (8 floats)
    const int bk = tid >> 3, bg = tid & 7;     // B: k-row, n-group (8 floats)

    if (tid < BM) {
        int mg = m0 + tid; bool v = mg < cnt;
        s.toks[tid] = v ? g_tok[e * TOKS + mg] : 0;
        s.affs[tid] = v ? g_aff[e * TOKS + mg] : 0.f;
    }
    __syncthreads();

    wmma::fragment<wmma::accumulator, 16, 16, 16, float> acc[2];
    wmma::fill_fragment(acc[0], 0.f);
    wmma::fill_fragment(acc[1], 0.f);

    const size_t arowb = (size_t)s.toks[ar] * DMODEL + aq * 8;
    float4 pa0 = *(const float4*)(x + arowb);
    float4 pa1 = *(const float4*)(x + arowb + 4);
    const float* brow0 = keys + ((size_t)e * DMODEL + bk) * FEXP + n0 + bg * 8;
    float4 pb0 = *(const float4*)(brow0);
    float4 pb1 = *(const float4*)(brow0 + 4);

    const int NC = DMODEL / BK;    // 32
    for (int c = 0; c < NC; c++) {
        __syncthreads();
        split4(pa0, &s.u.t.a_hi[ar * LDA + aq * 8],     &s.u.t.a_lo[ar * LDA + aq * 8]);
        split4(pa1, &s.u.t.a_hi[ar * LDA + aq * 8 + 4], &s.u.t.a_lo[ar * LDA + aq * 8 + 4]);
        split4(pb0, &s.u.t.b_hi[bk * LDB + bg * 8],     &s.u.t.b_lo[bk * LDB + bg * 8]);
        split4(pb1, &s.u.t.b_hi[bk * LDB + bg * 8 + 4], &s.u.t.b_lo[bk * LDB + bg * 8 + 4]);
        __syncthreads();
        if (c + 1 < NC) {
            int k0 = (c + 1) * BK;
            pa0 = *(const float4*)(x + arowb + k0);
            pa1 = *(const float4*)(x + arowb + k0 + 4);
            const float* bp = keys + ((size_t)e * DMODEL + k0 + bk) * FEXP + n0 + bg * 8;
            pb0 = *(const float4*)(bp);
            pb1 = *(const float4*)(bp + 4);
        }
        mma_stage(s, wm, wn, acc);
    }
    __syncthreads();   // mma reads done before epi overlays tiles

    float* ep = s.u.epi + w * 512;
    wmma::store_matrix_sync(ep, acc[0], 16, wmma::mem_row_major);
    wmma::store_matrix_sync(ep + 256, acc[1], 16, wmma::mem_row_major);
    __syncwarp();

    const int mloc = wm + lane;
    if (m0 + mloc < cnt) {
        float aff = s.affs[mloc];
        size_t rowb = ((size_t)e * TOKS + m0 + mloc) * FEXP + n0 + wn;
        unsigned short* dh = reinterpret_cast<unsigned short*>(g_h_hi) + rowb;
        unsigned short* dl = reinterpret_cast<unsigned short*>(g_h_lo) + rowb;
        #pragma unroll
        for (int p = 0; p < 16; p += 2) {
            float v0 = ep[lane * 16 + p];
            float v1 = ep[lane * 16 + p + 1];
            float h0 = v0 / (1.f + __expf(-v0)) * aff;
            float h1 = v1 / (1.f + __expf(-v1)) * aff;
            unsigned short hb0 = bf16bits(h0), hb1 = bf16bits(h1);
            unsigned short lb0 = bf16bits(h0 - bf16val(hb0));
            unsigned short lb1 = bf16bits(h1 - bf16val(hb1));
            *reinterpret_cast<uint32_t*>(dh + p) = (uint32_t)hb0 | ((uint32_t)hb1 << 16);
            *reinterpret_cast<uint32_t*>(dl + p) = (uint32_t)lb0 | ((uint32_t)lb1 << 16);
        }
    }
}

// GEMM2: g_out_tc[tok][d] += H[slot] @ values[e] ; A = bf16 H (direct copy)
__global__ __launch_bounds__(256, 2) void moe_gemm2(const float* __restrict__ values) {
    const int e   = blockIdx.y;
    const int cnt = g_cnt[e];
    const int m0  = blockIdx.x * BM;
    if (m0 >= cnt) return;
    const int n0  = blockIdx.z * BN;

    __shared__ GemmSmem s;
    const int tid = threadIdx.x, w = tid >> 5, lane = tid & 31;
    const int wm = (w & 1) * 32, wn = (w >> 1) * 16;
    const int ar = tid >> 2, aq = tid & 3;
    const int bk = tid >> 3, bg = tid & 7;

    if (tid < BM) {
        int mg = m0 + tid;
        s.toks[tid] = (mg < cnt) ? g_tok[e * TOKS + mg] : 0;
    }
    __syncthreads();

    wmma::fragment<wmma::accumulator, 16, 16, 16, float> acc[2];
    wmma::fill_fragment(acc[0], 0.f);
    wmma::fill_fragment(acc[1], 0.f);

    const size_t ab = ((size_t)e * TOKS + m0 + ar) * FEXP + aq * 8;
    uint4 ph = *(const uint4*)(reinterpret_cast<const unsigned short*>(g_h_hi) + ab);
    uint4 pl = *(const uint4*)(reinterpret_cast<const unsigned short*>(g_h_lo) + ab);
    const float* brow0 = values + ((size_t)e * FEXP + bk) * DMODEL + n0 + bg * 8;
    float4 pb0 = *(const float4*)(brow0);
    float4 pb1 = *(const float4*)(brow0 + 4);

    const int NC = FEXP / BK;    // 16
    for (int c = 0; c < NC; c++) {
        __syncthreads();
        *reinterpret_cast<uint4*>(&s.u.t.a_hi[ar * LDA + aq * 8]) = ph;
        *reinterpret_cast<uint4*>(&s.u.t.a_lo[ar * LDA + aq * 8]) = pl;
        split4(pb0, &s.u.t.b_hi[bk * LDB + bg * 8],     &s.u.t.b_lo[bk * LDB + bg * 8]);
        split4(pb1, &s.u.t.b_hi[bk * LDB + bg * 8 + 4], &s.u.t.b_lo[bk * LDB + bg * 8 + 4]);
        __syncthreads();
        if (c + 1 < NC) {
            int k0 = (c + 1) * BK;
            ph = *(const uint4*)(reinterpret_cast<const unsigned short*>(g_h_hi) + ab + k0);
            pl = *(const uint4*)(reinterpret_cast<const unsigned short*>(g_h_lo) + ab + k0);
            const float* bp = values + ((size_t)e * FEXP + k0 + bk) * DMODEL + n0 + bg * 8;
            pb0 = *(const float4*)(bp);
            pb1 = *(const float4*)(bp + 4);
        }
        mma_stage(s, wm, wn, acc);
    }
    __syncthreads();

    float* ep = s.u.epi + w * 512;
    wmma::store_matrix_sync(ep, acc[0], 16, wmma::mem_row_major);
    wmma::store_matrix_sync(ep + 256, acc[1], 16, wmma::mem_row_major);
    __syncwarp();

    const int mloc = wm + lane;
    if (m0 + mloc < cnt) {
        float* dst = g_out_tc + (size_t)s.toks[mloc] * DMODEL + n0 + wn;
        #pragma unroll
        for (int p = 0; p < 16; p++)
            atomicAdd(dst + p, ep[lane * 16 + p]);
    }
}

// ---------------- verify TC on 4 probe tokens --------------------------------
__global__ __launch_bounds__(256) void verify_kernel(
    const float* __restrict__ x, const float* __restrict__ sel_in,
    const float* __restrict__ keys, const float* __restrict__ values,
    const float* __restrict__ expert_sel, const float* __restrict__ bias)
{
    const int t   = (blockIdx.x * 2731 + 17) & (TOKS - 1);
    const int tid = threadIdx.x;
    const int warp = tid >> 5, lane = tid & 31;
    __shared__ float logit[NEXP];
    __shared__ int   sel[KSEL];
    __shared__ float aff[KSEL];
    __shared__ float hbuf[FEXP];

    const float* xs = sel_in + (size_t)t * DMODEL;
    #pragma unroll
    for (int w = 0; w < 2; w++) {
        int e = warp * 2 + w;
        const float* wr = expert_sel + (size_t)e * DMODEL;
        float s = 0.f;
        for (int i = lane; i < DMODEL; i += 32) s += xs[i] * wr[i];
        #pragma unroll
        for (int o = 16; o > 0; o >>= 1) s += __shfl_xor_sync(0xffffffffu, s, o);
        if (lane == 0) logit[e] = s;
    }
    __syncthreads();

    if (tid == 0) {
        float a[NEXP];
        #pragma unroll
        for (int e = 0; e < NEXP; e++) a[e] = 1.f / (1.f + expf(-logit[e]));
        bool taken[NROUTED];
        #pragma unroll
        for (int i = 0; i < NROUTED; i++) taken[i] = false;
        #pragma unroll
        for (int k = 0; k < KROUTE; k++) {
            float best = -1e30f; int bi = 0;
            for (int i = 0; i < NROUTED; i++) {
                float v = a[i] + bias[i];
                if (!taken[i] && v > best) { best = v; bi = i; }
            }
            taken[bi] = true; sel[k] = bi; aff[k] = a[bi];
        }
        sel[4] = NROUTED;     aff[4] = a[NROUTED];
        sel[5] = NROUTED + 1; aff[5] = a[NROUTED + 1];
    }
    __syncthreads();

    const float* xt = x + (size_t)t * DMODEL;
    const int d = tid;
    float acc = 0.f;
    for (int k = 0; k < KSEL; k++) {
        int e = sel[k];
        int pos = g_slot[t * KSEL + k];
        for (int f = tid; f < FEXP; f += 256) {
            float s = 0.f;
            const float* kw = keys + ((size_t)e * DMODEL) * FEXP + f;
            for (int kk = 0; kk < DMODEL; kk++) s += xt[kk] * kw[(size_t)kk * FEXP];
            float hv = s / (1.f + expf(-s)) * aff[k];
            hbuf[f] = hv;
            size_t hidx = ((size_t)e * TOKS + pos) * FEXP + f;
            float hs = bf16val(reinterpret_cast<unsigned short*>(g_h_hi)[hidx])
                     + bf16val(reinterpret_cast<unsigned short*>(g_h_lo)[hidx]);
            if (fabsf(hs - hv) > 5e-4f * fmaxf(fabsf(hv), 0.25f)) g_ok1 = 0;
        }
        __syncthreads();
        float a2 = 0.f;
        const float* vw = values + ((size_t)e * FEXP) * DMODEL + d;
        for (int f = 0; f < FEXP; f++) a2 += hbuf[f] * vw[(size_t)f * DMODEL];
        acc += a2;
        __syncthreads();
    }

    float got = g_out_tc[(size_t)t * DMODEL + d];
    if (fabsf(got - acc) > 5e-4f * fmaxf(fabsf(acc), 0.5f)) g_ok2 = 0;
}

// ---------------- fp32 SIMT fallback (round-1 proven) ------------------------
__global__ __launch_bounds__(256) void fb_gemm1(
    const float* __restrict__ xs, const float* __restrict__ keys)
{
    if (g_ok1) return;
    const int e   = blockIdx.y;
    const int cnt = g_cnt[e];
    const int m0  = blockIdx.x * 64;
    if (m0 >= cnt) return;
    const int n0  = blockIdx.z * 64;

    __shared__ float As[16][64];
    __shared__ float Bs[16][64];
    __shared__ int   toks[64];
    __shared__ float affs[64];

    const int tid = threadIdx.x;
    if (tid < 64) {
        int mg = m0 + tid;
        toks[tid] = (mg < cnt) ? g_tok[e * TOKS + mg] : 0;
        affs[tid] = (mg < cnt) ? g_aff[e * TOKS + mg] : 0.f;
    }
    __syncthreads();

    const int ty  = tid >> 4, tx  = tid & 15;
    const int am  = tid >> 2, akq = tid & 3;
    const int bk  = tid >> 4, bnq = tid & 15;
    const bool avalid = (m0 + am) < cnt;
    const float* arow = xs + (size_t)toks[am] * DMODEL;

    float acc[4][4];
    #pragma unroll
    for (int i = 0; i < 4; i++)
        #pragma unroll
        for (int jj = 0; jj < 4; jj++) acc[i][jj] = 0.f;

    for (int k0 = 0; k0 < DMODEL; k0 += 16) {
        float4 av = avalid ? *(const float4*)(arow + k0 + akq * 4)
                           : make_float4(0.f, 0.f, 0.f, 0.f);
        float4 bv = *(const float4*)(keys +
                    ((size_t)e * DMODEL + k0 + bk) * FEXP + n0 + bnq * 4);
        As[akq * 4 + 0][am] = av.x;
        As[akq * 4 + 1][am] = av.y;
        As[akq * 4 + 2][am] = av.z;
        As[akq * 4 + 3][am] = av.w;
        *(float4*)&Bs[bk][bnq * 4] = bv;
        __syncthreads();
        #pragma unroll
        for (int kk = 0; kk < 16; kk++) {
            float4 a = *(const float4*)&As[kk][ty * 4];
            float4 b = *(const float4*)&Bs[kk][tx * 4];
            float ar[4] = {a.x, a.y, a.z, a.w};
            float br[4] = {b.x, b.y, b.z, b.w};
            #pragma unroll
            for (int i = 0; i < 4; i++)
                #pragma unroll
                for (int jj = 0; jj < 4; jj++) acc[i][jj] += ar[i] * br[jj];
        }
        __syncthreads();
    }

    const size_t hbase = ((size_t)e * TOKS + m0) * FEXP + n0;
    #pragma unroll
    for (int i = 0; i < 4; i++) {
        int m = ty * 4 + i;
        if (m0 + m < cnt) {
            float afv = affs[m];
            #pragma unroll
            for (int jj = 0; jj < 4; jj++) {
                float v = acc[i][jj];
                g_hf[hbase + (size_t)m * FEXP + tx * 4 + jj] =
                    v / (1.f + __expf(-v)) * afv;
            }
        }
    }
}

// rebuild fp32 H from verified bf16 H when only stage-2 failed
__global__ __launch_bounds__(256) void h_conv_kernel() {
    if (!(g_ok1 && !g_ok2)) return;
    size_t i = (size_t)blockIdx.x * blockDim.x + threadIdx.x;
    if (i >= (size_t)NEXP * TOKS * FEXP / 4) return;
    ushort4 h = reinterpret_cast<const ushort4*>(g_h_hi)[i];
    ushort4 l = reinterpret_cast<const ushort4*>(g_h_lo)[i];
    float4 v;
    v.x = bf16val(h.x) + bf16val(l.x);
    v.y = bf16val(h.y) + bf16val(l.y);
    v.z = bf16val(h.z) + bf16val(l.z);
    v.w = bf16val(h.w) + bf16val(l.w);
    reinterpret_cast<float4*>(g_hf)[i] = v;
}

__global__ __launch_bounds__(256) void fb_gemm2(
    const float* __restrict__ values, float* __restrict__ out)
{
    if (g_ok1 && g_ok2) return;
    const int e   = blockIdx.y;
    const int cnt = g_cnt[e];
    const int m0  = blockIdx.x * 64;
    if (m0 >= cnt) return;
    const int n0  = blockIdx.z * 64;

    __shared__ float As[16][64];
    __shared__ float Bs[16][64];
    __shared__ int   toks[64];

    const int tid = threadIdx.x;
    if (tid < 64) {
        int mg = m0 + tid;
        toks[tid] = (mg < cnt) ? g_tok[e * TOKS + mg] : 0;
    }
    __syncthreads();

    const int ty  = tid >> 4, tx  = tid & 15;
    const int am  = tid >> 2, akq = tid & 3;
    const int bk  = tid >> 4, bnq = tid & 15;
    const bool avalid = (m0 + am) < cnt;
    const float* arow = g_hf + ((size_t)e * TOKS + m0 + am) * FEXP;

    float acc[4][4];
    #pragma unroll
    for (int i = 0; i < 4; i++)
        #pragma unroll
        for (int jj = 0; jj < 4; jj++) acc[i][jj] = 0.f;

    for (int k0 = 0; k0 < FEXP; k0 += 16) {
        float4 av = avalid ? *(const float4*)(arow + k0 + akq * 4)
                           : make_float4(0.f, 0.f, 0.f, 0.f);
        float4 bv = *(const float4*)(values +
                    ((size_t)e * FEXP + k0 + bk) * DMODEL + n0 + bnq * 4);
        As[akq * 4 + 0][am] = av.x;
        As[akq * 4 + 1][am] = av.y;
        As[akq * 4 + 2][am] = av.z;
        As[akq * 4 + 3][am] = av.w;
        *(float4*)&Bs[bk][bnq * 4] = bv;
        __syncthreads();
        #pragma unroll
        for (int kk = 0; kk < 16; kk++) {
            float4 a = *(const float4*)&As[kk][ty * 4];
            float4 b = *(const float4*)&Bs[kk][tx * 4];
            float ar[4] = {a.x, a.y, a.z, a.w};
            float br[4] = {b.x, b.y, b.z, b.w};
            #pragma unroll
            for (int i = 0; i < 4; i++)
                #pragma unroll
                for (int jj = 0; jj < 4; jj++) acc[i][jj] += ar[i] * br[jj];
        }
        __syncthreads();
    }

    #pragma unroll
    for (int i = 0; i < 4; i++) {
        int m = ty * 4 + i;
        if (m0 + m < cnt) {
            int t = toks[m];
            #pragma unroll
            for (int jj = 0; jj < 4; jj++)
                atomicAdd(&out[(size_t)t * DMODEL + n0 + tx * 4 + jj], acc[i][jj]);
        }
    }
}

// ---------------- commit + diagnostic delay ----------------------------------
__global__ void commit_kernel(float* __restrict__ out) {
    if (!(g_ok1 && g_ok2)) return;
    int i = blockIdx.x * blockDim.x + threadIdx.x;
    if (i < TOKS * DMODEL) out[i] = g_out_tc[i];
}

__global__ void diag_delay_kernel() {
    long long target = 0;
    if (!g_ok_mma) target += 5000000LL;
    if (!g_ok1)    target += 2500000LL;
    else if (!g_ok2) target += 1250000LL;
    if (target == 0) return;
    long long s = clock64();
    while (clock64() - s < target) { }
}

// ---------------- launch -----------------------------------------------------
extern "C" void kernel_launch(void* const* d_in, const int* in_sizes, int n_in,
                              void* d_out, int out_size) {
    const float* token_stream = (const float*)d_in[0];
    const float* sel_input    = (const float*)d_in[1];
    const float* keys         = (const float*)d_in[2];
    const float* values       = (const float*)d_in[3];
    const float* esel         = (const float*)d_in[4];
    const float* bias         = (const float*)d_in[5];
    float* out = (float*)d_out;

    const int write_sel = (out_size >= TOKS * DMODEL + TOKS * KSEL) ? 1 : 0;

    zero_out_kernel<<<(TOKS * DMODEL + 511) / 512, 512>>>(out, TOKS * DMODEL);
    zero_misc_kernel<<<1, 32>>>();
    zero_tc_kernel<<<(TOKS * DMODEL + 511) / 512, 512>>>();

    routing_kernel<<<TOKS, 256>>>(sel_input, esel, bias, out, write_sel);
    mma_selftest_kernel<<<1, 32>>>();

    // TC path
    dim3 g1(TOKS / BM, NEXP, FEXP / BN);       // (128, 16, 8)
    moe_gemm1<<<g1, 256>>>(token_stream, keys);
    dim3 g2(TOKS / BM, NEXP, DMODEL / BN);     // (128, 16, 16)
    moe_gemm2<<<g2, 256>>>(values);

    verify_kernel<<<4, 256>>>(token_stream, sel_input, keys, values, esel, bias);

    // tiered fallback
    dim3 f1(TOKS / 64, NEXP, FEXP / 64);
    fb_gemm1<<<f1, 256>>>(token_stream, keys);
    h_conv_kernel<<<(int)(((size_t)NEXP * TOKS * FEXP / 4 + 255) / 256), 256>>>();
    dim3 f2(TOKS / 64, NEXP, DMODEL / 64);
    fb_gemm2<<<f2, 256>>>(values, out);

    commit_kernel<<<(TOKS * DMODEL + 511) / 512, 512>>>(out);
    diag_delay_kernel<<<1, 1>>>();
}

// round 14
// speedup vs baseline: 1.4087x; 1.2767x over previous
#include <cuda_runtime.h>
#include <cuda_bf16.h>
#include <mma.h>
#include <math.h>
#include <stdint.h>

using namespace nvcuda;

#define TOKS    8192
#define DMODEL  1024
#define FEXP    512
#define NEXP    16
#define NROUTED 14
#define KROUTE  4
#define KSEL    6

#define BM 128
#define BN 64
#define BK 32
#define LDA 40       // A smem row stride (32 + 8 pad)
#define LDB 72       // B smem row stride (64 + 8 pad)

// ---------------- device scratch ---------------------------------------------
__device__ __align__(16) int   g_cnt[NEXP];
__device__ int   g_ok1, g_ok2;
__device__ __align__(16) int   g_tok[NEXP * TOKS];
__device__ __align__(16) int   g_slot[TOKS * KSEL];
__device__ __align__(16) float g_aff[NEXP * TOKS];
__device__ __align__(16) __nv_bfloat16 g_h_hi[(size_t)NEXP * TOKS * FEXP];
__device__ __align__(16) __nv_bfloat16 g_h_lo[(size_t)NEXP * TOKS * FEXP];
__device__ __align__(16) float g_hf[(size_t)NEXP * TOKS * FEXP];     // fb H (fp32)
__device__ __align__(16) float g_out_tc[(size_t)TOKS * DMODEL];      // TC accum

// ---------------- helpers ----------------------------------------------------
__device__ __forceinline__ unsigned short bf16bits(float f) {
    __nv_bfloat16 b = __float2bfloat16(f);
    return *reinterpret_cast<unsigned short*>(&b);
}
__device__ __forceinline__ float bf16val(unsigned short u) {
    __nv_bfloat16 b = *reinterpret_cast<__nv_bfloat16*>(&u);
    return __bfloat162float(b);
}
__device__ __forceinline__ void split4(float4 v, __nv_bfloat16* hi, __nv_bfloat16* lo) {
    unsigned short h0 = bf16bits(v.x), h1 = bf16bits(v.y);
    unsigned short h2 = bf16bits(v.z), h3 = bf16bits(v.w);
    unsigned short l0 = bf16bits(v.x - bf16val(h0));
    unsigned short l1 = bf16bits(v.y - bf16val(h1));
    unsigned short l2 = bf16bits(v.z - bf16val(h2));
    unsigned short l3 = bf16bits(v.w - bf16val(h3));
    *reinterpret_cast<uint2*>(hi) = make_uint2(
        (uint32_t)h0 | ((uint32_t)h1 << 16), (uint32_t)h2 | ((uint32_t)h3 << 16));
    *reinterpret_cast<uint2*>(lo) = make_uint2(
        (uint32_t)l0 | ((uint32_t)l1 << 16), (uint32_t)l2 | ((uint32_t)l3 << 16));
}

// dynamic-smem tile block (one pipeline stage)
struct __align__(16) Tiles {
    __nv_bfloat16 a_hi[BM * LDA];   // 10240 B
    __nv_bfloat16 a_lo[BM * LDA];   // 10240 B
    __nv_bfloat16 b_hi[BK * LDB];   //  4608 B
    __nv_bfloat16 b_lo[BK * LDB];   //  4608 B
};                                   // 29696 B
#define SMEM_GEMM (1024 + 2 * (int)sizeof(Tiles))   // 60416

// ---------------- utility kernels -------------------------------------------
__global__ void zero_out_kernel(float* out, int n) {
    int i = blockIdx.x * blockDim.x + threadIdx.x;
    if (i < n) out[i] = 0.f;
}
__global__ void zero_misc_kernel() {
    if (threadIdx.x < NEXP) g_cnt[threadIdx.x] = 0;
    if (threadIdx.x == 0) { g_ok1 = 1; g_ok2 = 1; }
}
__global__ void zero_tc_kernel() {
    int i = blockIdx.x * blockDim.x + threadIdx.x;
    if (i < TOKS * DMODEL) g_out_tc[i] = 0.f;
}

// ---------------- routing ---------------------------------------------------
__global__ __launch_bounds__(256) void routing_kernel(
    const float* __restrict__ sel_in,
    const float* __restrict__ expert_sel,
    const float* __restrict__ bias,
    float* __restrict__ out, int write_sel)
{
    const int t    = blockIdx.x;
    const int tid  = threadIdx.x;
    const int warp = tid >> 5, lane = tid & 31;
    __shared__ float logit[NEXP];

    const float* x = sel_in + (size_t)t * DMODEL;
    #pragma unroll
    for (int w = 0; w < 2; w++) {
        int e = warp * 2 + w;
        const float* wr = expert_sel + (size_t)e * DMODEL;
        float s = 0.f;
        for (int i = lane; i < DMODEL; i += 32) s += x[i] * wr[i];
        #pragma unroll
        for (int o = 16; o > 0; o >>= 1) s += __shfl_xor_sync(0xffffffffu, s, o);
        if (lane == 0) logit[e] = s;
    }
    __syncthreads();

    if (tid == 0) {
        float a[NEXP];
        #pragma unroll
        for (int e = 0; e < NEXP; e++) a[e] = 1.f / (1.f + expf(-logit[e]));

        int sel[KSEL]; float af[KSEL];
        bool taken[NROUTED];
        #pragma unroll
        for (int i = 0; i < NROUTED; i++) taken[i] = false;
        #pragma unroll
        for (int k = 0; k < KROUTE; k++) {
            float best = -1e30f; int bi = 0;
            for (int i = 0; i < NROUTED; i++) {
                float v = a[i] + bias[i];
                if (!taken[i] && v > best) { best = v; bi = i; }
            }
            taken[bi] = true; sel[k] = bi; af[k] = a[bi];
        }
        sel[4] = NROUTED;     af[4] = a[NROUTED];
        sel[5] = NROUTED + 1; af[5] = a[NROUTED + 1];

        #pragma unroll
        for (int k = 0; k < KSEL; k++) {
            int e   = sel[k];
            int pos = atomicAdd(&g_cnt[e], 1);
            g_tok[e * TOKS + pos] = t;
            g_aff[e * TOKS + pos] = af[k];
            g_slot[t * KSEL + k] = pos;
            if (write_sel)
                out[(size_t)TOKS * DMODEL + (size_t)t * KSEL + k] = (float)e;
        }
    }
}

// ---------------- 3-term wmma over one BK=32 chunk (R12-verified) -----------
// warp tile 32(m) x 32(n); 8 warps = 4m x 2n
__device__ __forceinline__ void mma_stage(
    const Tiles& t, int wm, int wn,
    wmma::fragment<wmma::accumulator, 16, 16, 16, float> (&acc)[2][2])
{
    wmma::fragment<wmma::matrix_a, 16, 16, 16, __nv_bfloat16, wmma::row_major> fa_hi, fa_lo;
    wmma::fragment<wmma::matrix_b, 16, 16, 16, __nv_bfloat16, wmma::row_major> fb_hi[2], fb_lo[2];
    #pragma unroll
    for (int ks = 0; ks < BK; ks += 16) {
        #pragma unroll
        for (int nt = 0; nt < 2; nt++) {
            wmma::load_matrix_sync(fb_hi[nt], &t.b_hi[ks * LDB + wn + nt * 16], LDB);
            wmma::load_matrix_sync(fb_lo[nt], &t.b_lo[ks * LDB + wn + nt * 16], LDB);
        }
        #pragma unroll
        for (int mt = 0; mt < 2; mt++) {
            wmma::load_matrix_sync(fa_hi, &t.a_hi[(wm + mt * 16) * LDA + ks], LDA);
            wmma::load_matrix_sync(fa_lo, &t.a_lo[(wm + mt * 16) * LDA + ks], LDA);
            #pragma unroll
            for (int nt = 0; nt < 2; nt++) {
                wmma::mma_sync(acc[mt][nt], fa_hi, fb_hi[nt], acc[mt][nt]);
                wmma::mma_sync(acc[mt][nt], fa_hi, fb_lo[nt], acc[mt][nt]);
                wmma::mma_sync(acc[mt][nt], fa_lo, fb_hi[nt], acc[mt][nt]);
            }
        }
    }
}

// GEMM1: H[slot][f] = silu( x[tok] @ keys[e] )[f] * aff -> bf16 hi/lo
__global__ __launch_bounds__(256) void moe_gemm1(
    const float* __restrict__ x, const float* __restrict__ keys)
{
    const int e   = blockIdx.y;
    const int cnt = g_cnt[e];
    const int m0  = blockIdx.x * BM;
    if (m0 >= cnt) return;
    const int n0  = blockIdx.z * BN;

    extern __shared__ char smem_raw[];
    int*   toks = (int*)smem_raw;
    float* affs = (float*)(smem_raw + 512);
    Tiles* st[2] = { (Tiles*)(smem_raw + 1024), (Tiles*)(smem_raw + 1024) + 1 };
    float* epi   = (float*)(smem_raw + 1024);

    const int tid = threadIdx.x, w = tid >> 5, lane = tid & 31;
    const int wm = (w >> 1) * 32, wn = (w & 1) * 32;
    const int ar = tid >> 1, aq = tid & 1;     // A: row, 16-col half
    const int bk = tid >> 3, bg = tid & 7;     // B: k-row, 8-col group

    if (tid < BM) {
        int mg = m0 + tid; bool v = mg < cnt;
        toks[tid] = v ? g_tok[e * TOKS + mg] : 0;
        affs[tid] = v ? g_aff[e * TOKS + mg] : 0.f;
    }
    __syncthreads();

    wmma::fragment<wmma::accumulator, 16, 16, 16, float> acc[2][2];
    #pragma unroll
    for (int i = 0; i < 2; i++)
        #pragma unroll
        for (int j = 0; j < 2; j++) wmma::fill_fragment(acc[i][j], 0.f);

    const size_t arowb = (size_t)toks[ar] * DMODEL + aq * 16;
    float4 pa[4], pb[2];
    #pragma unroll
    for (int q = 0; q < 4; q++) pa[q] = *(const float4*)(x + arowb + q * 4);
    {
        const float* bp = keys + ((size_t)e * DMODEL + bk) * FEXP + n0 + bg * 8;
        pb[0] = *(const float4*)(bp);
        pb[1] = *(const float4*)(bp + 4);
    }
    // fill stage 0
    {
        Tiles& t0 = *st[0];
        #pragma unroll
        for (int q = 0; q < 4; q++)
            split4(pa[q], &t0.a_hi[ar * LDA + aq * 16 + q * 4],
                          &t0.a_lo[ar * LDA + aq * 16 + q * 4]);
        split4(pb[0], &t0.b_hi[bk * LDB + bg * 8],     &t0.b_lo[bk * LDB + bg * 8]);
        split4(pb[1], &t0.b_hi[bk * LDB + bg * 8 + 4], &t0.b_lo[bk * LDB + bg * 8 + 4]);
    }
    __syncthreads();

    const int NC = DMODEL / BK;    // 32
    for (int c = 0; c < NC; c++) {
        if (c + 1 < NC) {
            int k0 = (c + 1) * BK;
            #pragma unroll
            for (int q = 0; q < 4; q++)
                pa[q] = *(const float4*)(x + arowb + k0 + q * 4);
            const float* bp = keys + ((size_t)e * DMODEL + k0 + bk) * FEXP + n0 + bg * 8;
            pb[0] = *(const float4*)(bp);
            pb[1] = *(const float4*)(bp + 4);
        }
        mma_stage(*st[c & 1], wm, wn, acc);
        if (c + 1 < NC) {
            Tiles& nx = *st[(c + 1) & 1];
            #pragma unroll
            for (int q = 0; q < 4; q++)
                split4(pa[q], &nx.a_hi[ar * LDA + aq * 16 + q * 4],
                              &nx.a_lo[ar * LDA + aq * 16 + q * 4]);
            split4(pb[0], &nx.b_hi[bk * LDB + bg * 8],     &nx.b_lo[bk * LDB + bg * 8]);
            split4(pb[1], &nx.b_hi[bk * LDB + bg * 8 + 4], &nx.b_lo[bk * LDB + bg * 8 + 4]);
        }
        __syncthreads();
    }

    // epilogue (R12-verified): silu * aff -> bf16 hi/lo
    float* ep = epi + w * 1024;
    #pragma unroll
    for (int mt = 0; mt < 2; mt++)
        #pragma unroll
        for (int nt = 0; nt < 2; nt++)
            wmma::store_matrix_sync(ep + (mt * 2 + nt) * 256, acc[mt][nt], 16,
                                    wmma::mem_row_major);
    __syncwarp();

    const int mloc = wm + lane;
    const int mt = lane >> 4, lr = lane & 15;
    if (m0 + mloc < cnt) {
        float aff = affs[mloc];
        size_t rowb = ((size_t)e * TOKS + m0 + mloc) * FEXP + n0 + wn;
        unsigned short* dh = reinterpret_cast<unsigned short*>(g_h_hi) + rowb;
        unsigned short* dl = reinterpret_cast<unsigned short*>(g_h_lo) + rowb;
        #pragma unroll
        for (int nt = 0; nt < 2; nt++) {
            #pragma unroll
            for (int p = 0; p < 16; p += 2) {
                float v0 = ep[(mt * 2 + nt) * 256 + lr * 16 + p];
                float v1 = ep[(mt * 2 + nt) * 256 + lr * 16 + p + 1];
                float h0 = v0 / (1.f + __expf(-v0)) * aff;
                float h1 = v1 / (1.f + __expf(-v1)) * aff;
                unsigned short hb0 = bf16bits(h0), hb1 = bf16bits(h1);
                unsigned short lb0 = bf16bits(h0 - bf16val(hb0));
                unsigned short lb1 = bf16bits(h1 - bf16val(hb1));
                *reinterpret_cast<uint32_t*>(dh + nt * 16 + p)
                    = (uint32_t)hb0 | ((uint32_t)hb1 << 16);
                *reinterpret_cast<uint32_t*>(dl + nt * 16 + p)
                    = (uint32_t)lb0 | ((uint32_t)lb1 << 16);
            }
        }
    }
}

// GEMM2: g_out_tc[tok][d] += H[slot] @ values[e] ; A = bf16 H (direct copy)
__global__ __launch_bounds__(256) void moe_gemm2(const float* __restrict__ values) {
    const int e   = blockIdx.y;
    const int cnt = g_cnt[e];
    const int m0  = blockIdx.x * BM;
    if (m0 >= cnt) return;
    const int n0  = blockIdx.z * BN;

    extern __shared__ char smem_raw[];
    int*   toks = (int*)smem_raw;
    Tiles* st[2] = { (Tiles*)(smem_raw + 1024), (Tiles*)(smem_raw + 1024) + 1 };
    float* epi   = (float*)(smem_raw + 1024);

    const int tid = threadIdx.x, w = tid >> 5, lane = tid & 31;
    const int wm = (w >> 1) * 32, wn = (w & 1) * 32;
    const int ar = tid >> 1, aq = tid & 1;
    const int bk = tid >> 3, bg = tid & 7;

    if (tid < BM) {
        int mg = m0 + tid;
        toks[tid] = (mg < cnt) ? g_tok[e * TOKS + mg] : 0;
    }
    __syncthreads();

    wmma::fragment<wmma::accumulator, 16, 16, 16, float> acc[2][2];
    #pragma unroll
    for (int i = 0; i < 2; i++)
        #pragma unroll
        for (int j = 0; j < 2; j++) wmma::fill_fragment(acc[i][j], 0.f);

    const size_t ab = ((size_t)e * TOKS + m0 + ar) * FEXP + aq * 16;
    uint4 ph[2], pl[2];
    ph[0] = *(const uint4*)(reinterpret_cast<const unsigned short*>(g_h_hi) + ab);
    ph[1] = *(const uint4*)(reinterpret_cast<const unsigned short*>(g_h_hi) + ab + 8);
    pl[0] = *(const uint4*)(reinterpret_cast<const unsigned short*>(g_h_lo) + ab);
    pl[1] = *(const uint4*)(reinterpret_cast<const unsigned short*>(g_h_lo) + ab + 8);
    float4 pb[2];
    {
        const float* bp = values + ((size_t)e * FEXP + bk) * DMODEL + n0 + bg * 8;
        pb[0] = *(const float4*)(bp);
        pb[1] = *(const float4*)(bp + 4);
    }
    {
        Tiles& t0 = *st[0];
        *reinterpret_cast<uint4*>(&t0.a_hi[ar * LDA + aq * 16])     = ph[0];
        *reinterpret_cast<uint4*>(&t0.a_hi[ar * LDA + aq * 16 + 8]) = ph[1];
        *reinterpret_cast<uint4*>(&t0.a_lo[ar * LDA + aq * 16])     = pl[0];
        *reinterpret_cast<uint4*>(&t0.a_lo[ar * LDA + aq * 16 + 8]) = pl[1];
        split4(pb[0], &t0.b_hi[bk * LDB + bg * 8],     &t0.b_lo[bk * LDB + bg * 8]);
        split4(pb[1], &t0.b_hi[bk * LDB + bg * 8 + 4], &t0.b_lo[bk * LDB + bg * 8 + 4]);
    }
    __syncthreads();

    const int NC = FEXP / BK;    // 16
    for (int c = 0; c < NC; c++) {
        if (c + 1 < NC) {
            int k0 = (c + 1) * BK;
            ph[0] = *(const uint4*)(reinterpret_cast<const unsigned short*>(g_h_hi) + ab + k0);
            ph[1] = *(const uint4*)(reinterpret_cast<const unsigned short*>(g_h_hi) + ab + k0 + 8);
            pl[0] = *(const uint4*)(reinterpret_cast<const unsigned short*>(g_h_lo) + ab + k0);
            pl[1] = *(const uint4*)(reinterpret_cast<const unsigned short*>(g_h_lo) + ab + k0 + 8);
            const float* bp = values + ((size_t)e * FEXP + k0 + bk) * DMODEL + n0 + bg * 8;
            pb[0] = *(const float4*)(bp);
            pb[1] = *(const float4*)(bp + 4);
        }
        mma_stage(*st[c & 1], wm, wn, acc);
        if (c + 1 < NC) {
            Tiles& nx = *st[(c + 1) & 1];
            *reinterpret_cast<uint4*>(&nx.a_hi[ar * LDA + aq * 16])     = ph[0];
            *reinterpret_cast<uint4*>(&nx.a_hi[ar * LDA + aq * 16 + 8]) = ph[1];
            *reinterpret_cast<uint4*>(&nx.a_lo[ar * LDA + aq * 16])     = pl[0];
            *reinterpret_cast<uint4*>(&nx.a_lo[ar * LDA + aq * 16 + 8]) = pl[1];
            split4(pb[0], &nx.b_hi[bk * LDB + bg * 8],     &nx.b_lo[bk * LDB + bg * 8]);
            split4(pb[1], &nx.b_hi[bk * LDB + bg * 8 + 4], &nx.b_lo[bk * LDB + bg * 8 + 4]);
        }
        __syncthreads();
    }

    float* ep = epi + w * 1024;
    #pragma unroll
    for (int mt = 0; mt < 2; mt++)
        #pragma unroll
        for (int nt = 0; nt < 2; nt++)
            wmma::store_matrix_sync(ep + (mt * 2 + nt) * 256, acc[mt][nt], 16,
                                    wmma::mem_row_major);
    __syncwarp();

    const int mloc = wm + lane;
    const int mt = lane >> 4, lr = lane & 15;
    if (m0 + mloc < cnt) {
        float* dst = g_out_tc + (size_t)toks[mloc] * DMODEL + n0 + wn;
        #pragma unroll
        for (int nt = 0; nt < 2; nt++)
            #pragma unroll
            for (int p = 0; p < 16; p++)
                atomicAdd(dst + nt * 16 + p, ep[(mt * 2 + nt) * 256 + lr * 16 + p]);
    }
}

// ---------------- lightweight verify on 4 probe tokens -----------------------
// H checked at 256 sampled f per expert (fp32 recompute); out checked against
// STORED H (isolates gemm2), so the tiered fallback logic stays exact.
__global__ __launch_bounds__(256) void verify_kernel(
    const float* __restrict__ x, const float* __restrict__ sel_in,
    const float* __restrict__ keys, const float* __restrict__ values,
    const float* __restrict__ expert_sel, const float* __restrict__ bias)
{
    const int t   = (blockIdx.x * 2731 + 17) & (TOKS - 1);
    const int tid = threadIdx.x;
    const int warp = tid >> 5, lane = tid & 31;
    __shared__ float logit[NEXP];
    __shared__ int   sel[KSEL];
    __shared__ float aff[KSEL];

    const float* xs = sel_in + (size_t)t * DMODEL;
    #pragma unroll
    for (int w = 0; w < 2; w++) {
        int e = warp * 2 + w;
        const float* wr = expert_sel + (size_t)e * DMODEL;
        float s = 0.f;
        for (int i = lane; i < DMODEL; i += 32) s += xs[i] * wr[i];
        #pragma unroll
        for (int o = 16; o > 0; o >>= 1) s += __shfl_xor_sync(0xffffffffu, s, o);
        if (lane == 0) logit[e] = s;
    }
    __syncthreads();

    if (tid == 0) {
        float a[NEXP];
        #pragma unroll
        for (int e = 0; e < NEXP; e++) a[e] = 1.f / (1.f + expf(-logit[e]));
        bool taken[NROUTED];
        #pragma unroll
        for (int i = 0; i < NROUTED; i++) taken[i] = false;
        #pragma unroll
        for (int k = 0; k < KROUTE; k++) {
            float best = -1e30f; int bi = 0;
            for (int i = 0; i < NROUTED; i++) {
                float v = a[i] + bias[i];
                if (!taken[i] && v > best) { best = v; bi = i; }
            }
            taken[bi] = true; sel[k] = bi; aff[k] = a[bi];
        }
        sel[4] = NROUTED;     aff[4] = a[NROUTED];
        sel[5] = NROUTED + 1; aff[5] = a[NROUTED + 1];
    }
    __syncthreads();

    const float* xt = x + (size_t)t * DMODEL;
    const int d = tid;
    float acc = 0.f;
    for (int k = 0; k < KSEL; k++) {
        int e = sel[k];
        int pos = g_slot[t * KSEL + k];
        const size_t hrow = ((size_t)e * TOKS + pos) * FEXP;

        // H spot-check at f = 2*tid (256 samples), fp32 recompute
        {
            int f = tid * 2;
            float s = 0.f;
            const float* kw = keys + (size_t)e * DMODEL * FEXP + f;
            for (int kk = 0; kk < DMODEL; kk++) s += xt[kk] * kw[(size_t)kk * FEXP];
            float hv = s / (1.f + expf(-s)) * aff[k];
            float hs = bf16val(reinterpret_cast<unsigned short*>(g_h_hi)[hrow + f])
                     + bf16val(reinterpret_cast<unsigned short*>(g_h_lo)[hrow + f]);
            if (fabsf(hs - hv) > 5e-4f * fmaxf(fabsf(hv), 0.25f)) g_ok1 = 0;
        }

        // out contribution from STORED H (validates gemm2 given H)
        float a2 = 0.f;
        const float* vw = values + (size_t)e * FEXP * DMODEL + d;
        for (int f = 0; f < FEXP; f++) {
            float hs = bf16val(reinterpret_cast<unsigned short*>(g_h_hi)[hrow + f])
                     + bf16val(reinterpret_cast<unsigned short*>(g_h_lo)[hrow + f]);
            a2 += hs * vw[(size_t)f * DMODEL];
        }
        acc += a2;
    }

    float got = g_out_tc[(size_t)t * DMODEL + d];
    if (fabsf(got - acc) > 5e-4f * fmaxf(fabsf(acc), 0.5f)) g_ok2 = 0;
}

// ---------------- fp32 SIMT fallback (round-1 proven) ------------------------
__global__ __launch_bounds__(256) void fb_gemm1(
    const float* __restrict__ xs, const float* __restrict__ keys)
{
    if (g_ok1) return;
    const int e   = blockIdx.y;
    const int cnt = g_cnt[e];
    const int m0  = blockIdx.x * 64;
    if (m0 >= cnt) return;
    const int n0  = blockIdx.z * 64;

    __shared__ float As[16][64];
    __shared__ float Bs[16][64];
    __shared__ int   toks[64];
    __shared__ float affs[64];

    const int tid = threadIdx.x;
    if (tid < 64) {
        int mg = m0 + tid;
        toks[tid] = (mg < cnt) ? g_tok[e * TOKS + mg] : 0;
        affs[tid] = (mg < cnt) ? g_aff[e * TOKS + mg] : 0.f;
    }
    __syncthreads();

    const int ty  = tid >> 4, tx  = tid & 15;
    const int am  = tid >> 2, akq = tid & 3;
    const int bk  = tid >> 4, bnq = tid & 15;
    const bool avalid = (m0 + am) < cnt;
    const float* arow = xs + (size_t)toks[am] * DMODEL;

    float acc[4][4];
    #pragma unroll
    for (int i = 0; i < 4; i++)
        #pragma unroll
        for (int jj = 0; jj < 4; jj++) acc[i][jj] = 0.f;

    for (int k0 = 0; k0 < DMODEL; k0 += 16) {
        float4 av = avalid ? *(const float4*)(arow + k0 + akq * 4)
                           : make_float4(0.f, 0.f, 0.f, 0.f);
        float4 bv = *(const float4*)(keys +
                    ((size_t)e * DMODEL + k0 + bk) * FEXP + n0 + bnq * 4);
        As[akq * 4 + 0][am] = av.x;
        As[akq * 4 + 1][am] = av.y;
        As[akq * 4 + 2][am] = av.z;
        As[akq * 4 + 3][am] = av.w;
        *(float4*)&Bs[bk][bnq * 4] = bv;
        __syncthreads();
        #pragma unroll
        for (int kk = 0; kk < 16; kk++) {
            float4 a = *(const float4*)&As[kk][ty * 4];
            float4 b = *(const float4*)&Bs[kk][tx * 4];
            float ar[4] = {a.x, a.y, a.z, a.w};
            float br[4] = {b.x, b.y, b.z, b.w};
            #pragma unroll
            for (int i = 0; i < 4; i++)
                #pragma unroll
                for (int jj = 0; jj < 4; jj++) acc[i][jj] += ar[i] * br[jj];
        }
        __syncthreads();
    }

    const size_t hbase = ((size_t)e * TOKS + m0) * FEXP + n0;
    #pragma unroll
    for (int i = 0; i < 4; i++) {
        int m = ty * 4 + i;
        if (m0 + m < cnt) {
            float afv = affs[m];
            #pragma unroll
            for (int jj = 0; jj < 4; jj++) {
                float v = acc[i][jj];
                g_hf[hbase + (size_t)m * FEXP + tx * 4 + jj] =
                    v / (1.f + __expf(-v)) * afv;
            }
        }
    }
}

__global__ __launch_bounds__(256) void h_conv_kernel() {
    if (!(g_ok1 && !g_ok2)) return;
    size_t i = (size_t)blockIdx.x * blockDim.x + threadIdx.x;
    if (i >= (size_t)NEXP * TOKS * FEXP / 4) return;
    ushort4 h = reinterpret_cast<const ushort4*>(g_h_hi)[i];
    ushort4 l = reinterpret_cast<const ushort4*>(g_h_lo)[i];
    float4 v;
    v.x = bf16val(h.x) + bf16val(l.x);
    v.y = bf16val(h.y) + bf16val(l.y);
    v.z = bf16val(h.z) + bf16val(l.z);
    v.w = bf16val(h.w) + bf16val(l.w);
    reinterpret_cast<float4*>(g_hf)[i] = v;
}

__global__ __launch_bounds__(256) void fb_gemm2(
    const float* __restrict__ values, float* __restrict__ out)
{
    if (g_ok1 && g_ok2) return;
    const int e   = blockIdx.y;
    const int cnt = g_cnt[e];
    const int m0  = blockIdx.x * 64;
    if (m0 >= cnt) return;
    const int n0  = blockIdx.z * 64;

    __shared__ float As[16][64];
    __shared__ float Bs[16][64];
    __shared__ int   toks[64];

    const int tid = threadIdx.x;
    if (tid < 64) {
        int mg = m0 + tid;
        toks[tid] = (mg < cnt) ? g_tok[e * TOKS + mg] : 0;
    }
    __syncthreads();

    const int ty  = tid >> 4, tx  = tid & 15;
    const int am  = tid >> 2, akq = tid & 3;
    const int bk  = tid >> 4, bnq = tid & 15;
    const bool avalid = (m0 + am) < cnt;
    const float* arow = g_hf + ((size_t)e * TOKS + m0 + am) * FEXP;

    float acc[4][4];
    #pragma unroll
    for (int i = 0; i < 4; i++)
        #pragma unroll
        for (int jj = 0; jj < 4; jj++) acc[i][jj] = 0.f;

    for (int k0 = 0; k0 < FEXP; k0 += 16) {
        float4 av = avalid ? *(const float4*)(arow + k0 + akq * 4)
                           : make_float4(0.f, 0.f, 0.f, 0.f);
        float4 bv = *(const float4*)(values +
                    ((size_t)e * FEXP + k0 + bk) * DMODEL + n0 + bnq * 4);
        As[akq * 4 + 0][am] = av.x;
        As[akq * 4 + 1][am] = av.y;
        As[akq * 4 + 2][am] = av.z;
        As[akq * 4 + 3][am] = av.w;
        *(float4*)&Bs[bk][bnq * 4] = bv;
        __syncthreads();
        #pragma unroll
        for (int kk = 0; kk < 16; kk++) {
            float4 a = *(const float4*)&As[kk][ty * 4];
            float4 b = *(const float4*)&Bs[kk][tx * 4];
            float ar[4] = {a.x, a.y, a.z, a.w};
            float br[4] = {b.x, b.y, b.z, b.w};
            #pragma unroll
            for (int i = 0; i < 4; i++)
                #pragma unroll
                for (int jj = 0; jj < 4; jj++) acc[i][jj] += ar[i] * br[jj];
        }
        __syncthreads();
    }

    #pragma unroll
    for (int i = 0; i < 4; i++) {
        int m = ty * 4 + i;
        if (m0 + m < cnt) {
            int t = toks[m];
            #pragma unroll
            for (int jj = 0; jj < 4; jj++)
                atomicAdd(&out[(size_t)t * DMODEL + n0 + tx * 4 + jj], acc[i][jj]);
        }
    }
}

// ---------------- commit + diagnostic delay ----------------------------------
__global__ void commit_kernel(float* __restrict__ out) {
    if (!(g_ok1 && g_ok2)) return;
    int i = blockIdx.x * blockDim.x + threadIdx.x;
    if (i < TOKS * DMODEL) out[i] = g_out_tc[i];
}

__global__ void diag_delay_kernel() {
    long long target = 0;
    if (!g_ok1)      target += 2500000LL;
    else if (!g_ok2) target += 1250000LL;
    if (target == 0) return;
    long long s = clock64();
    while (clock64() - s < target) { }
}

// ---------------- launch -----------------------------------------------------
extern "C" void kernel_launch(void* const* d_in, const int* in_sizes, int n_in,
                              void* d_out, int out_size) {
    const float* token_stream = (const float*)d_in[0];
    const float* sel_input    = (const float*)d_in[1];
    const float* keys         = (const float*)d_in[2];
    const float* values       = (const float*)d_in[3];
    const float* esel         = (const float*)d_in[4];
    const float* bias         = (const float*)d_in[5];
    float* out = (float*)d_out;

    cudaFuncSetAttribute(moe_gemm1, cudaFuncAttributeMaxDynamicSharedMemorySize, SMEM_GEMM);
    cudaFuncSetAttribute(moe_gemm2, cudaFuncAttributeMaxDynamicSharedMemorySize, SMEM_GEMM);

    const int write_sel = (out_size >= TOKS * DMODEL + TOKS * KSEL) ? 1 : 0;

    zero_out_kernel<<<(TOKS * DMODEL + 511) / 512, 512>>>(out, TOKS * DMODEL);
    zero_misc_kernel<<<1, 32>>>();
    zero_tc_kernel<<<(TOKS * DMODEL + 511) / 512, 512>>>();

    routing_kernel<<<TOKS, 256>>>(sel_input, esel, bias, out, write_sel);

    // TC path (double-buffered, dynamic smem)
    dim3 g1(TOKS / BM, NEXP, FEXP / BN);       // (64, 16, 8)
    moe_gemm1<<<g1, 256, SMEM_GEMM>>>(token_stream, keys);
    dim3 g2(TOKS / BM, NEXP, DMODEL / BN);     // (64, 16, 16)
    moe_gemm2<<<g2, 256, SMEM_GEMM>>>(values);

    verify_kernel<<<4, 256>>>(token_stream, sel_input, keys, values, esel, bias);

    // tiered fallback
    dim3 f1(TOKS / 64, NEXP, FEXP / 64);
    fb_gemm1<<<f1, 256>>>(token_stream, keys);
    h_conv_kernel<<<(int)(((size_t)NEXP * TOKS * FEXP / 4 + 255) / 256), 256>>>();
    dim3 f2(TOKS / 64, NEXP, DMODEL / 64);
    fb_gemm2<<<f2, 256>>>(values, out);

    commit_kernel<<<(TOKS * DMODEL + 511) / 512, 512>>>(out);
    diag_delay_kernel<<<1, 1>>>();
}

// round 16
// speedup vs baseline: 1.4868x; 1.0554x over previous
#include <cuda_runtime.h>
#include <cuda_bf16.h>
#include <mma.h>
#include <math.h>
#include <stdint.h>

using namespace nvcuda;

#define TOKS    8192
#define DMODEL  1024
#define FEXP    512
#define NEXP    16
#define NROUTED 14
#define KROUTE  4
#define KSEL    6

#define BM 128
#define BN 64
#define BK 32
#define LDA 40       // A smem row stride (32 + 8 pad)
#define LDB 72       // B smem row stride (64 + 8 pad)

// ---------------- device scratch ---------------------------------------------
__device__ __align__(16) int   g_cnt[NEXP];
__device__ int   g_ok1, g_ok2;
__device__ __align__(16) int   g_tok[NEXP * TOKS];
__device__ __align__(16) int   g_slot[TOKS * KSEL];
__device__ __align__(16) float g_aff[NEXP * TOKS];
__device__ __align__(16) __nv_bfloat16 g_h_hi[(size_t)NEXP * TOKS * FEXP];
__device__ __align__(16) __nv_bfloat16 g_h_lo[(size_t)NEXP * TOKS * FEXP];
__device__ __align__(16) float g_hf[(size_t)NEXP * TOKS * FEXP];     // fb H (fp32)
__device__ __align__(16) float g_out_tc[(size_t)TOKS * DMODEL];      // TC accum

// ---------------- helpers ----------------------------------------------------
__device__ __forceinline__ unsigned short bf16bits(float f) {
    __nv_bfloat16 b = __float2bfloat16(f);
    return *reinterpret_cast<unsigned short*>(&b);
}
__device__ __forceinline__ float bf16val(unsigned short u) {
    __nv_bfloat16 b = *reinterpret_cast<__nv_bfloat16*>(&u);
    return __bfloat162float(b);
}
__device__ __forceinline__ void split4(float4 v, __nv_bfloat16* hi, __nv_bfloat16* lo) {
    unsigned short h0 = bf16bits(v.x), h1 = bf16bits(v.y);
    unsigned short h2 = bf16bits(v.z), h3 = bf16bits(v.w);
    unsigned short l0 = bf16bits(v.x - bf16val(h0));
    unsigned short l1 = bf16bits(v.y - bf16val(h1));
    unsigned short l2 = bf16bits(v.z - bf16val(h2));
    unsigned short l3 = bf16bits(v.w - bf16val(h3));
    *reinterpret_cast<uint2*>(hi) = make_uint2(
        (uint32_t)h0 | ((uint32_t)h1 << 16), (uint32_t)h2 | ((uint32_t)h3 << 16));
    *reinterpret_cast<uint2*>(lo) = make_uint2(
        (uint32_t)l0 | ((uint32_t)l1 << 16), (uint32_t)l2 | ((uint32_t)l3 << 16));
}

// dynamic-smem tile block (one pipeline stage)
struct __align__(16) Tiles {
    __nv_bfloat16 a_hi[BM * LDA];   // 10240 B
    __nv_bfloat16 a_lo[BM * LDA];   // 10240 B
    __nv_bfloat16 b_hi[BK * LDB];   //  4608 B
    __nv_bfloat16 b_lo[BK * LDB];   //  4608 B
};                                   // 29696 B
#define SMEM_GEMM (1024 + 2 * (int)sizeof(Tiles))   // 60416

// ---------------- utility kernels -------------------------------------------
__global__ void zero_out_kernel(float* out, int n) {
    int i = blockIdx.x * blockDim.x + threadIdx.x;
    if (i < n) out[i] = 0.f;
}
__global__ void zero_misc_kernel() {
    if (threadIdx.x < NEXP) g_cnt[threadIdx.x] = 0;
    if (threadIdx.x == 0) { g_ok1 = 1; g_ok2 = 1; }
}
__global__ void zero_tc_kernel() {
    int i = blockIdx.x * blockDim.x + threadIdx.x;
    if (i < TOKS * DMODEL) g_out_tc[i] = 0.f;
}

// ---------------- routing ---------------------------------------------------
__global__ __launch_bounds__(256) void routing_kernel(
    const float* __restrict__ sel_in,
    const float* __restrict__ expert_sel,
    const float* __restrict__ bias,
    float* __restrict__ out, int write_sel)
{
    const int t    = blockIdx.x;
    const int tid  = threadIdx.x;
    const int warp = tid >> 5, lane = tid & 31;
    __shared__ float logit[NEXP];

    const float* x = sel_in + (size_t)t * DMODEL;
    #pragma unroll
    for (int w = 0; w < 2; w++) {
        int e = warp * 2 + w;
        const float* wr = expert_sel + (size_t)e * DMODEL;
        float s = 0.f;
        for (int i = lane; i < DMODEL; i += 32) s += x[i] * wr[i];
        #pragma unroll
        for (int o = 16; o > 0; o >>= 1) s += __shfl_xor_sync(0xffffffffu, s, o);
        if (lane == 0) logit[e] = s;
    }
    __syncthreads();

    if (tid == 0) {
        float a[NEXP];
        #pragma unroll
        for (int e = 0; e < NEXP; e++) a[e] = 1.f / (1.f + expf(-logit[e]));

        int sel[KSEL]; float af[KSEL];
        bool taken[NROUTED];
        #pragma unroll
        for (int i = 0; i < NROUTED; i++) taken[i] = false;
        #pragma unroll
        for (int k = 0; k < KROUTE; k++) {
            float best = -1e30f; int bi = 0;
            for (int i = 0; i < NROUTED; i++) {
                float v = a[i] + bias[i];
                if (!taken[i] && v > best) { best = v; bi = i; }
            }
            taken[bi] = true; sel[k] = bi; af[k] = a[bi];
        }
        sel[4] = NROUTED;     af[4] = a[NROUTED];
        sel[5] = NROUTED + 1; af[5] = a[NROUTED + 1];

        #pragma unroll
        for (int k = 0; k < KSEL; k++) {
            int e   = sel[k];
            int pos = atomicAdd(&g_cnt[e], 1);
            g_tok[e * TOKS + pos] = t;
            g_aff[e * TOKS + pos] = af[k];
            g_slot[t * KSEL + k] = pos;
            if (write_sel)
                out[(size_t)TOKS * DMODEL + (size_t)t * KSEL + k] = (float)e;
        }
    }
}

// ---------------- 3-term wmma over one BK=32 chunk (R12-verified) -----------
// warp tile 32(m) x 32(n); 8 warps = 4m x 2n
__device__ __forceinline__ void mma_stage(
    const Tiles& t, int wm, int wn,
    wmma::fragment<wmma::accumulator, 16, 16, 16, float> (&acc)[2][2])
{
    wmma::fragment<wmma::matrix_a, 16, 16, 16, __nv_bfloat16, wmma::row_major> fa_hi, fa_lo;
    wmma::fragment<wmma::matrix_b, 16, 16, 16, __nv_bfloat16, wmma::row_major> fb_hi[2], fb_lo[2];
    #pragma unroll
    for (int ks = 0; ks < BK; ks += 16) {
        #pragma unroll
        for (int nt = 0; nt < 2; nt++) {
            wmma::load_matrix_sync(fb_hi[nt], &t.b_hi[ks * LDB + wn + nt * 16], LDB);
            wmma::load_matrix_sync(fb_lo[nt], &t.b_lo[ks * LDB + wn + nt * 16], LDB);
        }
        #pragma unroll
        for (int mt = 0; mt < 2; mt++) {
            wmma::load_matrix_sync(fa_hi, &t.a_hi[(wm + mt * 16) * LDA + ks], LDA);
            wmma::load_matrix_sync(fa_lo, &t.a_lo[(wm + mt * 16) * LDA + ks], LDA);
            #pragma unroll
            for (int nt = 0; nt < 2; nt++) {
                wmma::mma_sync(acc[mt][nt], fa_hi, fb_hi[nt], acc[mt][nt]);
                wmma::mma_sync(acc[mt][nt], fa_hi, fb_lo[nt], acc[mt][nt]);
                wmma::mma_sync(acc[mt][nt], fa_lo, fb_hi[nt], acc[mt][nt]);
            }
        }
    }
}

// GEMM1: H[slot][f] = silu( x[tok] @ keys[e] )[f] * aff -> bf16 hi/lo
__global__ __launch_bounds__(256, 2) void moe_gemm1(
    const float* __restrict__ x, const float* __restrict__ keys)
{
    const int e   = blockIdx.y;
    const int cnt = g_cnt[e];
    const int m0  = blockIdx.x * BM;
    if (m0 >= cnt) return;
    const int n0  = blockIdx.z * BN;

    extern __shared__ char smem_raw[];
    int*   toks = (int*)smem_raw;
    float* affs = (float*)(smem_raw + 512);
    Tiles* st[2] = { (Tiles*)(smem_raw + 1024), (Tiles*)(smem_raw + 1024) + 1 };
    float* epi   = (float*)(smem_raw + 1024);

    const int tid = threadIdx.x, w = tid >> 5, lane = tid & 31;
    const int wm = (w >> 1) * 32, wn = (w & 1) * 32;
    const int ar = tid >> 1, aq = tid & 1;     // A: row, 16-col half
    const int bk = tid >> 3, bg = tid & 7;     // B: k-row, 8-col group

    if (tid < BM) {
        int mg = m0 + tid; bool v = mg < cnt;
        toks[tid] = v ? g_tok[e * TOKS + mg] : 0;
        affs[tid] = v ? g_aff[e * TOKS + mg] : 0.f;
    }
    __syncthreads();

    wmma::fragment<wmma::accumulator, 16, 16, 16, float> acc[2][2];
    #pragma unroll
    for (int i = 0; i < 2; i++)
        #pragma unroll
        for (int j = 0; j < 2; j++) wmma::fill_fragment(acc[i][j], 0.f);

    const size_t arowb = (size_t)toks[ar] * DMODEL + aq * 16;
    float4 pa[4], pb[2];
    #pragma unroll
    for (int q = 0; q < 4; q++) pa[q] = *(const float4*)(x + arowb + q * 4);
    {
        const float* bp = keys + ((size_t)e * DMODEL + bk) * FEXP + n0 + bg * 8;
        pb[0] = *(const float4*)(bp);
        pb[1] = *(const float4*)(bp + 4);
    }
    // fill stage 0
    {
        Tiles& t0 = *st[0];
        #pragma unroll
        for (int q = 0; q < 4; q++)
            split4(pa[q], &t0.a_hi[ar * LDA + aq * 16 + q * 4],
                          &t0.a_lo[ar * LDA + aq * 16 + q * 4]);
        split4(pb[0], &t0.b_hi[bk * LDB + bg * 8],     &t0.b_lo[bk * LDB + bg * 8]);
        split4(pb[1], &t0.b_hi[bk * LDB + bg * 8 + 4], &t0.b_lo[bk * LDB + bg * 8 + 4]);
    }
    __syncthreads();

    const int NC = DMODEL / BK;    // 32
    for (int c = 0; c < NC; c++) {
        if (c + 1 < NC) {
            int k0 = (c + 1) * BK;
            #pragma unroll
            for (int q = 0; q < 4; q++)
                pa[q] = *(const float4*)(x + arowb + k0 + q * 4);
            const float* bp = keys + ((size_t)e * DMODEL + k0 + bk) * FEXP + n0 + bg * 8;
            pb[0] = *(const float4*)(bp);
            pb[1] = *(const float4*)(bp + 4);
        }
        mma_stage(*st[c & 1], wm, wn, acc);
        if (c + 1 < NC) {
            Tiles& nx = *st[(c + 1) & 1];
            #pragma unroll
            for (int q = 0; q < 4; q++)
                split4(pa[q], &nx.a_hi[ar * LDA + aq * 16 + q * 4],
                              &nx.a_lo[ar * LDA + aq * 16 + q * 4]);
            split4(pb[0], &nx.b_hi[bk * LDB + bg * 8],     &nx.b_lo[bk * LDB + bg * 8]);
            split4(pb[1], &nx.b_hi[bk * LDB + bg * 8 + 4], &nx.b_lo[bk * LDB + bg * 8 + 4]);
        }
        __syncthreads();
    }

    // epilogue (R12-verified): silu * aff -> bf16 hi/lo
    float* ep = epi + w * 1024;
    #pragma unroll
    for (int mt = 0; mt < 2; mt++)
        #pragma unroll
        for (int nt = 0; nt < 2; nt++)
            wmma::store_matrix_sync(ep + (mt * 2 + nt) * 256, acc[mt][nt], 16,
                                    wmma::mem_row_major);
    __syncwarp();

    const int mloc = wm + lane;
    const int mt = lane >> 4, lr = lane & 15;
    if (m0 + mloc < cnt) {
        float aff = affs[mloc];
        size_t rowb = ((size_t)e * TOKS + m0 + mloc) * FEXP + n0 + wn;
        unsigned short* dh = reinterpret_cast<unsigned short*>(g_h_hi) + rowb;
        unsigned short* dl = reinterpret_cast<unsigned short*>(g_h_lo) + rowb;
        #pragma unroll
        for (int nt = 0; nt < 2; nt++) {
            #pragma unroll
            for (int p = 0; p < 16; p += 2) {
                float v0 = ep[(mt * 2 + nt) * 256 + lr * 16 + p];
                float v1 = ep[(mt * 2 + nt) * 256 + lr * 16 + p + 1];
                float h0 = v0 / (1.f + __expf(-v0)) * aff;
                float h1 = v1 / (1.f + __expf(-v1)) * aff;
                unsigned short hb0 = bf16bits(h0), hb1 = bf16bits(h1);
                unsigned short lb0 = bf16bits(h0 - bf16val(hb0));
                unsigned short lb1 = bf16bits(h1 - bf16val(hb1));
                *reinterpret_cast<uint32_t*>(dh + nt * 16 + p)
                    = (uint32_t)hb0 | ((uint32_t)hb1 << 16);
                *reinterpret_cast<uint32_t*>(dl + nt * 16 + p)
                    = (uint32_t)lb0 | ((uint32_t)lb1 << 16);
            }
        }
    }
}

// GEMM2: g_out_tc[tok][d] += H[slot] @ values[e] ; A = bf16 H (direct copy)
__global__ __launch_bounds__(256, 2) void moe_gemm2(const float* __restrict__ values) {
    const int e   = blockIdx.y;
    const int cnt = g_cnt[e];
    const int m0  = blockIdx.x * BM;
    if (m0 >= cnt) return;
    const int n0  = blockIdx.z * BN;

    extern __shared__ char smem_raw[];
    int*   toks = (int*)smem_raw;
    Tiles* st[2] = { (Tiles*)(smem_raw + 1024), (Tiles*)(smem_raw + 1024) + 1 };
    float* epi   = (float*)(smem_raw + 1024);

    const int tid = threadIdx.x, w = tid >> 5, lane = tid & 31;
    const int wm = (w >> 1) * 32, wn = (w & 1) * 32;
    const int ar = tid >> 1, aq = tid & 1;
    const int bk = tid >> 3, bg = tid & 7;

    if (tid < BM) {
        int mg = m0 + tid;
        toks[tid] = (mg < cnt) ? g_tok[e * TOKS + mg] : 0;
    }
    __syncthreads();

    wmma::fragment<wmma::accumulator, 16, 16, 16, float> acc[2][2];
    #pragma unroll
    for (int i = 0; i < 2; i++)
        #pragma unroll
        for (int j = 0; j < 2; j++) wmma::fill_fragment(acc[i][j], 0.f);

    const size_t ab = ((size_t)e * TOKS + m0 + ar) * FEXP + aq * 16;
    uint4 ph[2], pl[2];
    ph[0] = *(const uint4*)(reinterpret_cast<const unsigned short*>(g_h_hi) + ab);
    ph[1] = *(const uint4*)(reinterpret_cast<const unsigned short*>(g_h_hi) + ab + 8);
    pl[0] = *(const uint4*)(reinterpret_cast<const unsigned short*>(g_h_lo) + ab);
    pl[1] = *(const uint4*)(reinterpret_cast<const unsigned short*>(g_h_lo) + ab + 8);
    float4 pb[2];
    {
        const float* bp = values + ((size_t)e * FEXP + bk) * DMODEL + n0 + bg * 8;
        pb[0] = *(const float4*)(bp);
        pb[1] = *(const float4*)(bp + 4);
    }
    {
        Tiles& t0 = *st[0];
        *reinterpret_cast<uint4*>(&t0.a_hi[ar * LDA + aq * 16])     = ph[0];
        *reinterpret_cast<uint4*>(&t0.a_hi[ar * LDA + aq * 16 + 8]) = ph[1];
        *reinterpret_cast<uint4*>(&t0.a_lo[ar * LDA + aq * 16])     = pl[0];
        *reinterpret_cast<uint4*>(&t0.a_lo[ar * LDA + aq * 16 + 8]) = pl[1];
        split4(pb[0], &t0.b_hi[bk * LDB + bg * 8],     &t0.b_lo[bk * LDB + bg * 8]);
        split4(pb[1], &t0.b_hi[bk * LDB + bg * 8 + 4], &t0.b_lo[bk * LDB + bg * 8 + 4]);
    }
    __syncthreads();

    const int NC = FEXP / BK;    // 16
    for (int c = 0; c < NC; c++) {
        if (c + 1 < NC) {
            int k0 = (c + 1) * BK;
            ph[0] = *(const uint4*)(reinterpret_cast<const unsigned short*>(g_h_hi) + ab + k0);
            ph[1] = *(const uint4*)(reinterpret_cast<const unsigned short*>(g_h_hi) + ab + k0 + 8);
            pl[0] = *(const uint4*)(reinterpret_cast<const unsigned short*>(g_h_lo) + ab + k0);
            pl[1] = *(const uint4*)(reinterpret_cast<const unsigned short*>(g_h_lo) + ab + k0 + 8);
            const float* bp = values + ((size_t)e * FEXP + k0 + bk) * DMODEL + n0 + bg * 8;
            pb[0] = *(const float4*)(bp);
            pb[1] = *(const float4*)(bp + 4);
        }
        mma_stage(*st[c & 1], wm, wn, acc);
        if (c + 1 < NC) {
            Tiles& nx = *st[(c + 1) & 1];
            *reinterpret_cast<uint4*>(&nx.a_hi[ar * LDA + aq * 16])     = ph[0];
            *reinterpret_cast<uint4*>(&nx.a_hi[ar * LDA + aq * 16 + 8]) = ph[1];
            *reinterpret_cast<uint4*>(&nx.a_lo[ar * LDA + aq * 16])     = pl[0];
            *reinterpret_cast<uint4*>(&nx.a_lo[ar * LDA + aq * 16 + 8]) = pl[1];
            split4(pb[0], &nx.b_hi[bk * LDB + bg * 8],     &nx.b_lo[bk * LDB + bg * 8]);
            split4(pb[1], &nx.b_hi[bk * LDB + bg * 8 + 4], &nx.b_lo[bk * LDB + bg * 8 + 4]);
        }
        __syncthreads();
    }

    float* ep = epi + w * 1024;
    #pragma unroll
    for (int mt = 0; mt < 2; mt++)
        #pragma unroll
        for (int nt = 0; nt < 2; nt++)
            wmma::store_matrix_sync(ep + (mt * 2 + nt) * 256, acc[mt][nt], 16,
                                    wmma::mem_row_major);
    __syncwarp();

    const int mloc = wm + lane;
    const int mt = lane >> 4, lr = lane & 15;
    if (m0 + mloc < cnt) {
        float* dst = g_out_tc + (size_t)toks[mloc] * DMODEL + n0 + wn;
        #pragma unroll
        for (int nt = 0; nt < 2; nt++)
            #pragma unroll
            for (int p = 0; p < 16; p++)
                atomicAdd(dst + nt * 16 + p, ep[(mt * 2 + nt) * 256 + lr * 16 + p]);
    }
}

// ---------------- lightweight verify on 4 probe tokens -----------------------
__global__ __launch_bounds__(256) void verify_kernel(
    const float* __restrict__ x, const float* __restrict__ sel_in,
    const float* __restrict__ keys, const float* __restrict__ values,
    const float* __restrict__ expert_sel, const float* __restrict__ bias)
{
    const int t   = (blockIdx.x * 2731 + 17) & (TOKS - 1);
    const int tid = threadIdx.x;
    const int warp = tid >> 5, lane = tid & 31;
    __shared__ float logit[NEXP];
    __shared__ int   sel[KSEL];
    __shared__ float aff[KSEL];

    const float* xs = sel_in + (size_t)t * DMODEL;
    #pragma unroll
    for (int w = 0; w < 2; w++) {
        int e = warp * 2 + w;
        const float* wr = expert_sel + (size_t)e * DMODEL;
        float s = 0.f;
        for (int i = lane; i < DMODEL; i += 32) s += xs[i] * wr[i];
        #pragma unroll
        for (int o = 16; o > 0; o >>= 1) s += __shfl_xor_sync(0xffffffffu, s, o);
        if (lane == 0) logit[e] = s;
    }
    __syncthreads();

    if (tid == 0) {
        float a[NEXP];
        #pragma unroll
        for (int e = 0; e < NEXP; e++) a[e] = 1.f / (1.f + expf(-logit[e]));
        bool taken[NROUTED];
        #pragma unroll
        for (int i = 0; i < NROUTED; i++) taken[i] = false;
        #pragma unroll
        for (int k = 0; k < KROUTE; k++) {
            float best = -1e30f; int bi = 0;
            for (int i = 0; i < NROUTED; i++) {
                float v = a[i] + bias[i];
                if (!taken[i] && v > best) { best = v; bi = i; }
            }
            taken[bi] = true; sel[k] = bi; aff[k] = a[bi];
        }
        sel[4] = NROUTED;     aff[4] = a[NROUTED];
        sel[5] = NROUTED + 1; aff[5] = a[NROUTED + 1];
    }
    __syncthreads();

    const float* xt = x + (size_t)t * DMODEL;
    const int d = tid;
    float acc = 0.f;
    for (int k = 0; k < KSEL; k++) {
        int e = sel[k];
        int pos = g_slot[t * KSEL + k];
        const size_t hrow = ((size_t)e * TOKS + pos) * FEXP;

        // H spot-check at f = 2*tid (256 samples), fp32 recompute
        {
            int f = tid * 2;
            float s = 0.f;
            const float* kw = keys + (size_t)e * DMODEL * FEXP + f;
            for (int kk = 0; kk < DMODEL; kk++) s += xt[kk] * kw[(size_t)kk * FEXP];
            float hv = s / (1.f + expf(-s)) * aff[k];
            float hs = bf16val(reinterpret_cast<unsigned short*>(g_h_hi)[hrow + f])
                     + bf16val(reinterpret_cast<unsigned short*>(g_h_lo)[hrow + f]);
            if (fabsf(hs - hv) > 5e-4f * fmaxf(fabsf(hv), 0.25f)) g_ok1 = 0;
        }

        // out contribution from STORED H (validates gemm2 given H)
        float a2 = 0.f;
        const float* vw = values + (size_t)e * FEXP * DMODEL + d;
        for (int f = 0; f < FEXP; f++) {
            float hs = bf16val(reinterpret_cast<unsigned short*>(g_h_hi)[hrow + f])
                     + bf16val(reinterpret_cast<unsigned short*>(g_h_lo)[hrow + f]);
            a2 += hs * vw[(size_t)f * DMODEL];
        }
        acc += a2;
    }

    float got = g_out_tc[(size_t)t * DMODEL + d];
    if (fabsf(got - acc) > 5e-4f * fmaxf(fabsf(acc), 0.5f)) g_ok2 = 0;
}

// ---------------- fp32 SIMT fallback (round-1 proven) ------------------------
__global__ __launch_bounds__(256) void fb_gemm1(
    const float* __restrict__ xs, const float* __restrict__ keys)
{
    if (g_ok1) return;
    const int e   = blockIdx.y;
    const int cnt = g_cnt[e];
    const int m0  = blockIdx.x * 64;
    if (m0 >= cnt) return;
    const int n0  = blockIdx.z * 64;

    __shared__ float As[16][64];
    __shared__ float Bs[16][64];
    __shared__ int   toks[64];
    __shared__ float affs[64];

    const int tid = threadIdx.x;
    if (tid < 64) {
        int mg = m0 + tid;
        toks[tid] = (mg < cnt) ? g_tok[e * TOKS + mg] : 0;
        affs[tid] = (mg < cnt) ? g_aff[e * TOKS + mg] : 0.f;
    }
    __syncthreads();

    const int ty  = tid >> 4, tx  = tid & 15;
    const int am  = tid >> 2, akq = tid & 3;
    const int bk  = tid >> 4, bnq = tid & 15;
    const bool avalid = (m0 + am) < cnt;
    const float* arow = xs + (size_t)toks[am] * DMODEL;

    float acc[4][4];
    #pragma unroll
    for (int i = 0; i < 4; i++)
        #pragma unroll
        for (int jj = 0; jj < 4; jj++) acc[i][jj] = 0.f;

    for (int k0 = 0; k0 < DMODEL; k0 += 16) {
        float4 av = avalid ? *(const float4*)(arow + k0 + akq * 4)
                           : make_float4(0.f, 0.f, 0.f, 0.f);
        float4 bv = *(const float4*)(keys +
                    ((size_t)e * DMODEL + k0 + bk) * FEXP + n0 + bnq * 4);
        As[akq * 4 + 0][am] = av.x;
        As[akq * 4 + 1][am] = av.y;
        As[akq * 4 + 2][am] = av.z;
        As[akq * 4 + 3][am] = av.w;
        *(float4*)&Bs[bk][bnq * 4] = bv;
        __syncthreads();
        #pragma unroll
        for (int kk = 0; kk < 16; kk++) {
            float4 a = *(const float4*)&As[kk][ty * 4];
            float4 b = *(const float4*)&Bs[kk][tx * 4];
            float ar[4] = {a.x, a.y, a.z, a.w};
            float br[4] = {b.x, b.y, b.z, b.w};
            #pragma unroll
            for (int i = 0; i < 4; i++)
                #pragma unroll
                for (int jj = 0; jj < 4; jj++) acc[i][jj] += ar[i] * br[jj];
        }
        __syncthreads();
    }

    const size_t hbase = ((size_t)e * TOKS + m0) * FEXP + n0;
    #pragma unroll
    for (int i = 0; i < 4; i++) {
        int m = ty * 4 + i;
        if (m0 + m < cnt) {
            float afv = affs[m];
            #pragma unroll
            for (int jj = 0; jj < 4; jj++) {
                float v = acc[i][jj];
                g_hf[hbase + (size_t)m * FEXP + tx * 4 + jj] =
                    v / (1.f + __expf(-v)) * afv;
            }
        }
    }
}

__global__ __launch_bounds__(256) void h_conv_kernel() {
    if (!(g_ok1 && !g_ok2)) return;
    size_t i = (size_t)blockIdx.x * blockDim.x + threadIdx.x;
    if (i >= (size_t)NEXP * TOKS * FEXP / 4) return;
    ushort4 h = reinterpret_cast<const ushort4*>(g_h_hi)[i];
    ushort4 l = reinterpret_cast<const ushort4*>(g_h_lo)[i];
    float4 v;
    v.x = bf16val(h.x) + bf16val(l.x);
    v.y = bf16val(h.y) + bf16val(l.y);
    v.z = bf16val(h.z) + bf16val(l.z);
    v.w = bf16val(h.w) + bf16val(l.w);
    reinterpret_cast<float4*>(g_hf)[i] = v;
}

__global__ __launch_bounds__(256) void fb_gemm2(
    const float* __restrict__ values, float* __restrict__ out)
{
    if (g_ok1 && g_ok2) return;
    const int e   = blockIdx.y;
    const int cnt = g_cnt[e];
    const int m0  = blockIdx.x * 64;
    if (m0 >= cnt) return;
    const int n0  = blockIdx.z * 64;

    __shared__ float As[16][64];
    __shared__ float Bs[16][64];
    __shared__ int   toks[64];

    const int tid = threadIdx.x;
    if (tid < 64) {
        int mg = m0 + tid;
        toks[tid] = (mg < cnt) ? g_tok[e * TOKS + mg] : 0;
    }
    __syncthreads();

    const int ty  = tid >> 4, tx  = tid & 15;
    const int am  = tid >> 2, akq = tid & 3;
    const int bk  = tid >> 4, bnq = tid & 15;
    const bool avalid = (m0 + am) < cnt;
    const float* arow = g_hf + ((size_t)e * TOKS + m0 + am) * FEXP;

    float acc[4][4];
    #pragma unroll
    for (int i = 0; i < 4; i++)
        #pragma unroll
        for (int jj = 0; jj < 4; jj++) acc[i][jj] = 0.f;

    for (int k0 = 0; k0 < FEXP; k0 += 16) {
        float4 av = avalid ? *(const float4*)(arow + k0 + akq * 4)
                           : make_float4(0.f, 0.f, 0.f, 0.f);
        float4 bv = *(const float4*)(values +
                    ((size_t)e * FEXP + k0 + bk) * DMODEL + n0 + bnq * 4);
        As[akq * 4 + 0][am] = av.x;
        As[akq * 4 + 1][am] = av.y;
        As[akq * 4 + 2][am] = av.z;
        As[akq * 4 + 3][am] = av.w;
        *(float4*)&Bs[bk][bnq * 4] = bv;
        __syncthreads();
        #pragma unroll
        for (int kk = 0; kk < 16; kk++) {
            float4 a = *(const float4*)&As[kk][ty * 4];
            float4 b = *(const float4*)&Bs[kk][tx * 4];
            float ar[4] = {a.x, a.y, a.z, a.w};
            float br[4] = {b.x, b.y, b.z, b.w};
            #pragma unroll
            for (int i = 0; i < 4; i++)
                #pragma unroll
                for (int jj = 0; jj < 4; jj++) acc[i][jj] += ar[i] * br[jj];
        }
        __syncthreads();
    }

    #pragma unroll
    for (int i = 0; i < 4; i++) {
        int m = ty * 4 + i;
        if (m0 + m < cnt) {
            int t = toks[m];
            #pragma unroll
            for (int jj = 0; jj < 4; jj++)
                atomicAdd(&out[(size_t)t * DMODEL + n0 + tx * 4 + jj], acc[i][jj]);
        }
    }
}

// ---------------- commit + diagnostic delay ----------------------------------
__global__ void commit_kernel(float* __restrict__ out) {
    if (!(g_ok1 && g_ok2)) return;
    int i = blockIdx.x * blockDim.x + threadIdx.x;
    if (i < TOKS * DMODEL) out[i] = g_out_tc[i];
}

__global__ void diag_delay_kernel() {
    long long target = 0;
    if (!g_ok1)      target += 2500000LL;
    else if (!g_ok2) target += 1250000LL;
    if (target == 0) return;
    long long s = clock64();
    while (clock64() - s < target) { }
}

// ---------------- launch -----------------------------------------------------
extern "C" void kernel_launch(void* const* d_in, const int* in_sizes, int n_in,
                              void* d_out, int out_size) {
    const float* token_stream = (const float*)d_in[0];
    const float* sel_input    = (const float*)d_in[1];
    const float* keys         = (const float*)d_in[2];
    const float* values       = (const float*)d_in[3];
    const float* esel         = (const float*)d_in[4];
    const float* bias         = (const float*)d_in[5];
    float* out = (float*)d_out;

    cudaFuncSetAttribute(moe_gemm1, cudaFuncAttributeMaxDynamicSharedMemorySize, SMEM_GEMM);
    cudaFuncSetAttribute(moe_gemm2, cudaFuncAttributeMaxDynamicSharedMemorySize, SMEM_GEMM);

    const int write_sel = (out_size >= TOKS * DMODEL + TOKS * KSEL) ? 1 : 0;

    zero_out_kernel<<<(TOKS * DMODEL + 511) / 512, 512>>>(out, TOKS * DMODEL);
    zero_misc_kernel<<<1, 32>>>();
    zero_tc_kernel<<<(TOKS * DMODEL + 511) / 512, 512>>>();

    routing_kernel<<<TOKS, 256>>>(sel_input, esel, bias, out, write_sel);

    // TC path (double-buffered, dynamic smem, 2 CTAs/SM)
    dim3 g1(TOKS / BM, NEXP, FEXP / BN);       // (64, 16, 8)
    moe_gemm1<<<g1, 256, SMEM_GEMM>>>(token_stream, keys);
    dim3 g2(TOKS / BM, NEXP, DMODEL / BN);     // (64, 16, 16)
    moe_gemm2<<<g2, 256, SMEM_GEMM>>>(values);

    verify_kernel<<<4, 256>>>(token_stream, sel_input, keys, values, esel, bias);

    // tiered fallback
    dim3 f1(TOKS / 64, NEXP, FEXP / 64);
    fb_gemm1<<<f1, 256>>>(token_stream, keys);
    h_conv_kernel<<<(int)(((size_t)NEXP * TOKS * FEXP / 4 + 255) / 256), 256>>>();
    dim3 f2(TOKS / 64, NEXP, DMODEL / 64);
    fb_gemm2<<<f2, 256>>>(values, out);

    commit_kernel<<<(TOKS * DMODEL + 511) / 512, 512>>>(out);
    diag_delay_kernel<<<1, 1>>>();
}